// round 13
// baseline (speedup 1.0000x reference)
#include <cuda_runtime.h>
#include <cuda_bf16.h>

#define H    32
#define DX   16
#define HQ   16
#define NMAX 50048
#define EMAX 1605632

typedef unsigned long long u64;
typedef unsigned int u32;
typedef __nv_bfloat162 bf2;

__device__ __align__(16) float g_x[NMAX * DX];
__device__ __align__(16) float g_h[NMAX * H];
__device__ __align__(16) u32 g_A[NMAX * HQ];
__device__ __align__(16) u32 g_B[NMAX * HQ];
__device__ __align__(16) float g_magg[NMAX * H];
__device__ __align__(16) float g_tagg[NMAX * DX];
__device__ int g_deg[NMAX];
__device__ int g_rowptr[NMAX + 1];
__device__ int g_cursor[NMAX];
__device__ int g_srow[EMAX];
__device__ int g_scol[EMAX];
__device__ int g_dummy;

__device__ __forceinline__ float silu_f(float v) {
    return v * (1.0f / (1.0f + __expf(-v)));
}
__device__ __forceinline__ u32 b2u(bf2 v) { return *reinterpret_cast<u32*>(&v); }
__device__ __forceinline__ bf2 u2b(u32 v) { return *reinterpret_cast<bf2*>(&v); }

__device__ __forceinline__ bf2 silu_b(bf2 v) {
    bf2 h = __hmul2(v, __float2bfloat162_rn(0.5f));
    u32 tu;
    u32 hu = b2u(h);
    asm("tanh.approx.bf16x2 %0, %1;" : "=r"(tu) : "r"(hu));
    return __hmul2(h, __hadd2(u2b(tu), __float2bfloat162_rn(1.0f)));
}

__device__ __forceinline__ u64 pack2(float lo, float hi) {
    u64 r; asm("mov.b64 %0, {%1,%2};" : "=l"(r) : "f"(lo), "f"(hi)); return r;
}
__device__ __forceinline__ void unpack2(u64 v, float& lo, float& hi) {
    asm("mov.b64 {%0,%1}, %2;" : "=f"(lo), "=f"(hi) : "l"(v));
}
__device__ __forceinline__ void fma2(u64& d, u64 a, u64 b) {
    asm("fma.rn.f32x2 %0, %1, %2, %0;" : "+l"(d) : "l"(a), "l"(b));
}
__device__ __forceinline__ u64 dup2(float v) {
    u64 r; asm("mov.b64 %0, {%1,%1};" : "=l"(r) : "f"(v)); return r;
}
__device__ __forceinline__ void red_add_v4(float* a, float x, float y, float z, float w) {
    asm volatile("red.global.add.v4.f32 [%0], {%1,%2,%3,%4};"
                 :: "l"(a), "f"(x), "f"(y), "f"(z), "f"(w) : "memory");
}

// ---------------------------------------------------------------------------
__global__ __launch_bounds__(128, 4) void init_kernel(
    const float* __restrict__ attrs, const float* __restrict__ pos,
    const float* __restrict__ projW, const float* __restrict__ embW,
    const float* __restrict__ embB, const float* __restrict__ eW1,
    const float* __restrict__ eb1, int n)
{
    __shared__ __align__(16) float sWa[H][H];
    __shared__ __align__(16) float sWb[H][H];
    for (int idx = threadIdx.x; idx < H * H; idx += 128) {
        int j = idx >> 5, k = idx & 31;
        sWa[k][j] = eW1[j * 68 + k];
        sWb[k][j] = eW1[j * 68 + 32 + k];
    }
    __syncthreads();
    int i = blockIdx.x * 128 + threadIdx.x;
    if (i >= n) return;

    g_deg[i] = 0;

    float p0 = pos[i*3], p1 = pos[i*3+1], p2 = pos[i*3+2];
    float xv[DX];
#pragma unroll
    for (int j = 0; j < DX; j++)
        xv[j] = projW[j*3]*p0 + projW[j*3+1]*p1 + projW[j*3+2]*p2;
    float4* xo = (float4*)&g_x[i * DX];
#pragma unroll
    for (int q = 0; q < 4; q++)
        xo[q] = make_float4(xv[4*q], xv[4*q+1], xv[4*q+2], xv[4*q+3]);

    float a0 = attrs[i*3], a1 = attrs[i*3+1], a2 = attrs[i*3+2];
    float hv[H];
#pragma unroll
    for (int j = 0; j < H; j++)
        hv[j] = embW[j*3]*a0 + embW[j*3+1]*a1 + embW[j*3+2]*a2 + embB[j];
    float4* ho = (float4*)&g_h[i * H];
#pragma unroll
    for (int q = 0; q < 8; q++)
        ho[q] = make_float4(hv[4*q], hv[4*q+1], hv[4*q+2], hv[4*q+3]);

    float Av[H], Bv[H];
#pragma unroll
    for (int j = 0; j < H; j++) { Av[j] = eb1[j]; Bv[j] = 0.0f; }
#pragma unroll
    for (int k = 0; k < H; k++) {
        float hk = hv[k];
        const float4* wa = (const float4*)&sWa[k][0];
        const float4* wb = (const float4*)&sWb[k][0];
#pragma unroll
        for (int q = 0; q < 8; q++) {
            float4 a = wa[q], b = wb[q];
            Av[4*q] += a.x*hk; Av[4*q+1] += a.y*hk; Av[4*q+2] += a.z*hk; Av[4*q+3] += a.w*hk;
            Bv[4*q] += b.x*hk; Bv[4*q+1] += b.y*hk; Bv[4*q+2] += b.z*hk; Bv[4*q+3] += b.w*hk;
        }
    }
    u32 pa[HQ], pb[HQ];
#pragma unroll
    for (int jq = 0; jq < HQ; jq++) {
        pa[jq] = b2u(__floats2bfloat162_rn(Av[2*jq], Av[2*jq+1]));
        pb[jq] = b2u(__floats2bfloat162_rn(Bv[2*jq], Bv[2*jq+1]));
    }
    uint4* Ao = (uint4*)&g_A[i * HQ];
    uint4* Bo = (uint4*)&g_B[i * HQ];
#pragma unroll
    for (int q = 0; q < 4; q++) {
        Ao[q] = make_uint4(pa[4*q], pa[4*q+1], pa[4*q+2], pa[4*q+3]);
        Bo[q] = make_uint4(pb[4*q], pb[4*q+1], pb[4*q+2], pb[4*q+3]);
    }

    const float4 z4 = make_float4(0.f, 0.f, 0.f, 0.f);
    float4* mz = (float4*)&g_magg[i * H];
    float4* tz = (float4*)&g_tagg[i * DX];
#pragma unroll
    for (int q = 0; q < 8; q++) mz[q] = z4;
#pragma unroll
    for (int q = 0; q < 4; q++) tz[q] = z4;
}

// ---- counting sort by row --------------------------------------------------
__global__ void hist_kernel(const int* __restrict__ ei, int E)
{
    int e = blockIdx.x * blockDim.x + threadIdx.x;
    if (e < E) atomicAdd(&g_deg[ei[e]], 1);
}

#define SCAN_T 1024
#define BINS_PER_T 49

__global__ __launch_bounds__(SCAN_T) void scan_kernel(int n, int E)
{
    __shared__ int s_sum[SCAN_T];
    int t = threadIdx.x;
    int base = t * BINS_PER_T;

    int sum = 0;
#pragma unroll 7
    for (int r = 0; r < BINS_PER_T; r++) {
        int b = base + r;
        if (b < n) sum += g_deg[b];
    }
    s_sum[t] = sum;
    __syncthreads();
    for (int d = 1; d < SCAN_T; d <<= 1) {
        int v = (t >= d) ? s_sum[t - d] : 0;
        __syncthreads();
        s_sum[t] += v;
        __syncthreads();
    }
    int run = (t > 0) ? s_sum[t - 1] : 0;
    for (int r = 0; r < BINS_PER_T; r++) {
        int b = base + r;
        if (b < n) {
            g_rowptr[b] = run;
            g_cursor[b] = run;
            run += g_deg[b];
        }
    }
    if (t == 0) g_rowptr[n] = E;
}

__global__ void scatter_kernel(const int* __restrict__ ei, int E)
{
    int e = blockIdx.x * blockDim.x + threadIdx.x;
    if (e >= E) return;
    int row = ei[e];
    int col = ei[E + e];
    int p = atomicAdd(&g_cursor[row], 1);
    g_srow[p] = row;
    g_scol[p] = col;
}

__global__ void nop_kernel() { if (blockIdx.x == 1u << 30) g_dummy = 1; }

// ---------------------------------------------------------------------------
// edge kernel: T=2 edges/thread over row-sorted edges, bf16 MLP
// ---------------------------------------------------------------------------
#define ETPB 128

__global__ __launch_bounds__(ETPB, 3) void edge_kernel(
    int E,
    const float* __restrict__ pos,
    const float* __restrict__ W1,
    const float* __restrict__ W2,
    const float* __restrict__ b2,
    const float* __restrict__ cW1,
    const float* __restrict__ cb1,
    const float* __restrict__ cW2)
{
    __shared__ __align__(16) u32 s_W2t[H][HQ];
    __shared__ __align__(16) u32 s_cW1t[H][HQ];
    __shared__ __align__(16) u64 s_wr2[HQ];
    __shared__ __align__(16) u64 s_we2[3][HQ];
    __shared__ u32 s_b2b[HQ], s_cb1b[HQ], s_cw2b[HQ];

    for (int idx = threadIdx.x; idx < H * HQ; idx += ETPB) {
        int k = idx >> 4, jq = idx & 15;
        s_W2t[k][jq]  = b2u(__floats2bfloat162_rn(W2[(2*jq)*H+k],  W2[(2*jq+1)*H+k]));
        s_cW1t[k][jq] = b2u(__floats2bfloat162_rn(cW1[(2*jq)*H+k], cW1[(2*jq+1)*H+k]));
    }
    if (threadIdx.x < HQ) {
        int jq = threadIdx.x;
        s_wr2[jq]    = pack2(W1[(2*jq)*68+64], W1[(2*jq+1)*68+64]);
        s_we2[0][jq] = pack2(W1[(2*jq)*68+65], W1[(2*jq+1)*68+65]);
        s_we2[1][jq] = pack2(W1[(2*jq)*68+66], W1[(2*jq+1)*68+66]);
        s_we2[2][jq] = pack2(W1[(2*jq)*68+67], W1[(2*jq+1)*68+67]);
        s_b2b[jq]  = b2u(__floats2bfloat162_rn(b2[2*jq],  b2[2*jq+1]));
        s_cb1b[jq] = b2u(__floats2bfloat162_rn(cb1[2*jq], cb1[2*jq+1]));
        s_cw2b[jq] = b2u(__floats2bfloat162_rn(cW2[2*jq], cW2[2*jq+1]));
    }
    __syncthreads();

    int e0 = blockIdx.x * (2 * ETPB) + threadIdx.x;
    if (e0 >= E) return;
    int e1 = e0 + ETPB;
    bool v1 = (e1 < E);
    int e1c = v1 ? e1 : e0;

    int row0 = g_srow[e0],  col0 = g_scol[e0];
    int row1 = g_srow[e1c], col1 = g_scol[e1c];

    float ea00 = pos[row0*3]   - pos[col0*3];
    float ea01 = pos[row0*3+1] - pos[col0*3+1];
    float ea02 = pos[row0*3+2] - pos[col0*3+2];
    float ea10 = pos[row1*3]   - pos[col1*3];
    float ea11 = pos[row1*3+1] - pos[col1*3+1];
    float ea12 = pos[row1*3+2] - pos[col1*3+2];

    bf2 cd0[8], cd1[8];
    float rad0 = 0.0f, rad1 = 0.0f;
    {
        const float4* xr0 = (const float4*)&g_x[row0 * DX];
        const float4* xc0 = (const float4*)&g_x[col0 * DX];
        const float4* xr1 = (const float4*)&g_x[row1 * DX];
        const float4* xc1 = (const float4*)&g_x[col1 * DX];
#pragma unroll
        for (int q = 0; q < 4; q++) {
            float4 a = xr0[q], b = xc0[q];
            float d0 = a.x-b.x, d1 = a.y-b.y, d2 = a.z-b.z, d3 = a.w-b.w;
            cd0[2*q]   = __floats2bfloat162_rn(d0, d1);
            cd0[2*q+1] = __floats2bfloat162_rn(d2, d3);
            rad0 += d0*d0 + d1*d1 + d2*d2 + d3*d3;
            float4 c = xr1[q], d = xc1[q];
            float f0 = c.x-d.x, f1 = c.y-d.y, f2 = c.z-d.z, f3 = c.w-d.w;
            cd1[2*q]   = __floats2bfloat162_rn(f0, f1);
            cd1[2*q+1] = __floats2bfloat162_rn(f2, f3);
            rad1 += f0*f0 + f1*f1 + f2*f2 + f3*f3;
        }
    }

    // layer 1 per edge (transient f32x2 accumulators)
    bf2 a0_bf[HQ], a1_bf[HQ];
#pragma unroll
    for (int ed = 0; ed < 2; ed++) {
        int row = ed ? row1 : row0;
        int col = ed ? col1 : col0;
        float rad = ed ? rad1 : rad0;
        float ex = ed ? ea10 : ea00;
        float ey = ed ? ea11 : ea01;
        float ez = ed ? ea12 : ea02;
        u64 acc2[HQ];
        const uint4* Ar = (const uint4*)&g_A[row * HQ];
        const uint4* Bc = (const uint4*)&g_B[col * HQ];
#pragma unroll
        for (int q = 0; q < 4; q++) {
            uint4 a4 = Ar[q], b4 = Bc[q];
            const u32* ap = (const u32*)&a4;
            const u32* bp = (const u32*)&b4;
#pragma unroll
            for (int r = 0; r < 4; r++) {
                float2 af = __bfloat1622float2(u2b(ap[r]));
                float2 bf = __bfloat1622float2(u2b(bp[r]));
                acc2[4*q + r] = pack2(af.x + bf.x, af.y + bf.y);
            }
        }
        u64 rad2 = dup2(rad);
        u64 e02 = dup2(ex), e12 = dup2(ey), e22 = dup2(ez);
#pragma unroll
        for (int jq = 0; jq < HQ; jq++) {
            fma2(acc2[jq], s_wr2[jq], rad2);
            fma2(acc2[jq], s_we2[0][jq], e02);
            fma2(acc2[jq], s_we2[1][jq], e12);
            fma2(acc2[jq], s_we2[2][jq], e22);
        }
#pragma unroll
        for (int jq = 0; jq < HQ; jq++) {
            float lo, hi;
            unpack2(acc2[jq], lo, hi);
            bf2 s = silu_b(__floats2bfloat162_rn(lo, hi));
            if (ed) a1_bf[jq] = s; else a0_bf[jq] = s;
        }
    }

    // layer 2: shared weight loads
    bf2 ms0[HQ], ms1[HQ];
    {
        bf2 m2a[HQ], m2b[HQ];
#pragma unroll
        for (int jq = 0; jq < HQ; jq++) { m2a[jq] = u2b(s_b2b[jq]); m2b[jq] = u2b(s_b2b[jq]); }
#pragma unroll
        for (int k = 0; k < H; k++) {
            bf2 mk0 = (k & 1) ? __high2bfloat162(a0_bf[k >> 1]) : __low2bfloat162(a0_bf[k >> 1]);
            bf2 mk1 = (k & 1) ? __high2bfloat162(a1_bf[k >> 1]) : __low2bfloat162(a1_bf[k >> 1]);
            const uint4* w4 = (const uint4*)&s_W2t[k][0];
#pragma unroll
            for (int q = 0; q < 4; q++) {
                uint4 w = w4[q];
                m2a[4*q]   = __hfma2(u2b(w.x), mk0, m2a[4*q]);
                m2a[4*q+1] = __hfma2(u2b(w.y), mk0, m2a[4*q+1]);
                m2a[4*q+2] = __hfma2(u2b(w.z), mk0, m2a[4*q+2]);
                m2a[4*q+3] = __hfma2(u2b(w.w), mk0, m2a[4*q+3]);
                m2b[4*q]   = __hfma2(u2b(w.x), mk1, m2b[4*q]);
                m2b[4*q+1] = __hfma2(u2b(w.y), mk1, m2b[4*q+1]);
                m2b[4*q+2] = __hfma2(u2b(w.z), mk1, m2b[4*q+2]);
                m2b[4*q+3] = __hfma2(u2b(w.w), mk1, m2b[4*q+3]);
            }
        }
#pragma unroll
        for (int jq = 0; jq < HQ; jq++) {
            ms0[jq] = silu_b(m2a[jq]);
            ms1[jq] = silu_b(m2b[jq]);
        }
    }

    // coord head: shared weight loads
    float cm0 = 0.0f, cm1 = 0.0f;
    {
        bf2 c2a[HQ], c2b[HQ];
#pragma unroll
        for (int jq = 0; jq < HQ; jq++) { c2a[jq] = u2b(s_cb1b[jq]); c2b[jq] = u2b(s_cb1b[jq]); }
#pragma unroll
        for (int k = 0; k < H; k++) {
            bf2 mk0 = (k & 1) ? __high2bfloat162(ms0[k >> 1]) : __low2bfloat162(ms0[k >> 1]);
            bf2 mk1 = (k & 1) ? __high2bfloat162(ms1[k >> 1]) : __low2bfloat162(ms1[k >> 1]);
            const uint4* w4 = (const uint4*)&s_cW1t[k][0];
#pragma unroll
            for (int q = 0; q < 4; q++) {
                uint4 w = w4[q];
                c2a[4*q]   = __hfma2(u2b(w.x), mk0, c2a[4*q]);
                c2a[4*q+1] = __hfma2(u2b(w.y), mk0, c2a[4*q+1]);
                c2a[4*q+2] = __hfma2(u2b(w.z), mk0, c2a[4*q+2]);
                c2a[4*q+3] = __hfma2(u2b(w.w), mk0, c2a[4*q+3]);
                c2b[4*q]   = __hfma2(u2b(w.x), mk1, c2b[4*q]);
                c2b[4*q+1] = __hfma2(u2b(w.y), mk1, c2b[4*q+1]);
                c2b[4*q+2] = __hfma2(u2b(w.z), mk1, c2b[4*q+2]);
                c2b[4*q+3] = __hfma2(u2b(w.w), mk1, c2b[4*q+3]);
            }
        }
#pragma unroll
        for (int jq = 0; jq < HQ; jq++) {
            bf2 cw = u2b(s_cw2b[jq]);
            float2 pa = __bfloat1622float2(__hmul2(cw, silu_b(c2a[jq])));
            float2 pb = __bfloat1622float2(__hmul2(cw, silu_b(c2b[jq])));
            cm0 += pa.x + pa.y;
            cm1 += pb.x + pb.y;
        }
    }

    // scatters
    {
        float* mago = &g_magg[row0 * H];
#pragma unroll
        for (int q = 0; q < 8; q++) {
            float2 f0 = __bfloat1622float2(ms0[2*q]);
            float2 f1 = __bfloat1622float2(ms0[2*q+1]);
            red_add_v4(mago + 4*q, f0.x, f0.y, f1.x, f1.y);
        }
        float* tago = &g_tagg[row0 * DX];
#pragma unroll
        for (int q = 0; q < 4; q++) {
            float2 d0 = __bfloat1622float2(cd0[2*q]);
            float2 d1 = __bfloat1622float2(cd0[2*q+1]);
            red_add_v4(tago + 4*q, d0.x*cm0, d0.y*cm0, d1.x*cm0, d1.y*cm0);
        }
    }
    if (v1) {
        float* mago = &g_magg[row1 * H];
#pragma unroll
        for (int q = 0; q < 8; q++) {
            float2 f0 = __bfloat1622float2(ms1[2*q]);
            float2 f1 = __bfloat1622float2(ms1[2*q+1]);
            red_add_v4(mago + 4*q, f0.x, f0.y, f1.x, f1.y);
        }
        float* tago = &g_tagg[row1 * DX];
#pragma unroll
        for (int q = 0; q < 4; q++) {
            float2 d0 = __bfloat1622float2(cd1[2*q]);
            float2 d1 = __bfloat1622float2(cd1[2*q+1]);
            red_add_v4(tago + 4*q, d0.x*cm1, d0.y*cm1, d1.x*cm1, d1.y*cm1);
        }
    }
}

// ---------------------------------------------------------------------------
#define NTPB 128

__global__ __launch_bounds__(NTPB, 4) void node_kernel(
    const float* __restrict__ nW1, const float* __restrict__ nb1,
    const float* __restrict__ nW2, const float* __restrict__ nb2,
    const float* __restrict__ eW1n, const float* __restrict__ eb1n,
    const float* __restrict__ linW, float* __restrict__ out, int n)
{
    __shared__ __align__(16) float sN1t[2 * H][H];
    __shared__ __align__(16) float sN2t[H][H];
    __shared__ __align__(16) float sEAt[H][H];
    __shared__ __align__(16) float sEBt[H][H];

    int i = blockIdx.x * NTPB + threadIdx.x;
    bool active = (i < n);

    float cnt = 0.f;
    float4 xr[4], tr[4], hr[8], mr[8];
    if (active) {
        cnt = (float)(g_rowptr[i + 1] - g_rowptr[i]);
        const float4* xp = (const float4*)&g_x[i * DX];
        const float4* tp = (const float4*)&g_tagg[i * DX];
        const float4* hp = (const float4*)&g_h[i * H];
        const float4* mp = (const float4*)&g_magg[i * H];
#pragma unroll
        for (int q = 0; q < 4; q++) { xr[q] = xp[q]; tr[q] = tp[q]; }
#pragma unroll
        for (int q = 0; q < 8; q++) { hr[q] = hp[q]; mr[q] = mp[q]; }
    }

    for (int idx = threadIdx.x; idx < H * 2 * H; idx += NTPB) {
        int j = idx >> 6, k = idx & 63;
        sN1t[k][j] = nW1[idx];
    }
    for (int idx = threadIdx.x; idx < H * H; idx += NTPB) {
        int j = idx >> 5, k = idx & 31;
        sN2t[k][j] = nW2[idx];
        if (eW1n) {
            sEAt[k][j] = eW1n[j * 68 + k];
            sEBt[k][j] = eW1n[j * 68 + 32 + k];
        }
    }
    __syncthreads();

    if (!active) return;

    float inv = 1.0f / fmaxf(cnt, 1.0f);
    const float4 z4 = make_float4(0.f, 0.f, 0.f, 0.f);

    float xv[DX];
    float4* xp = (float4*)&g_x[i * DX];
    float4* tp = (float4*)&g_tagg[i * DX];
#pragma unroll
    for (int q = 0; q < 4; q++) {
        xv[4*q]   = xr[q].x + tr[q].x * inv;
        xv[4*q+1] = xr[q].y + tr[q].y * inv;
        xv[4*q+2] = xr[q].z + tr[q].z * inv;
        xv[4*q+3] = xr[q].w + tr[q].w * inv;
        xp[q] = make_float4(xv[4*q], xv[4*q+1], xv[4*q+2], xv[4*q+3]);
        tp[q] = z4;
    }

    float hv[H], mg[H];
    float4* mp = (float4*)&g_magg[i * H];
#pragma unroll
    for (int q = 0; q < 8; q++) {
        hv[4*q] = hr[q].x; hv[4*q+1] = hr[q].y; hv[4*q+2] = hr[q].z; hv[4*q+3] = hr[q].w;
        mg[4*q] = mr[q].x; mg[4*q+1] = mr[q].y; mg[4*q+2] = mr[q].z; mg[4*q+3] = mr[q].w;
        mp[q] = z4;
    }

    float u[H];
#pragma unroll
    for (int j = 0; j < H; j++) u[j] = nb1[j];
#pragma unroll
    for (int k = 0; k < H; k++) {
        float v = hv[k];
        const float4* w4 = (const float4*)&sN1t[k][0];
#pragma unroll
        for (int q = 0; q < 8; q++) {
            float4 w = w4[q];
            u[4*q] += w.x*v; u[4*q+1] += w.y*v; u[4*q+2] += w.z*v; u[4*q+3] += w.w*v;
        }
    }
#pragma unroll
    for (int k = 0; k < H; k++) {
        float v = mg[k];
        const float4* w4 = (const float4*)&sN1t[H + k][0];
#pragma unroll
        for (int q = 0; q < 8; q++) {
            float4 w = w4[q];
            u[4*q] += w.x*v; u[4*q+1] += w.y*v; u[4*q+2] += w.z*v; u[4*q+3] += w.w*v;
        }
    }
#pragma unroll
    for (int j = 0; j < H; j++) u[j] = silu_f(u[j]);

    float hn[H];
#pragma unroll
    for (int j = 0; j < H; j++) hn[j] = nb2[j];
#pragma unroll
    for (int k = 0; k < H; k++) {
        float v = u[k];
        const float4* w4 = (const float4*)&sN2t[k][0];
#pragma unroll
        for (int q = 0; q < 8; q++) {
            float4 w = w4[q];
            hn[4*q] += w.x*v; hn[4*q+1] += w.y*v; hn[4*q+2] += w.z*v; hn[4*q+3] += w.w*v;
        }
    }
#pragma unroll
    for (int j = 0; j < H; j++) hn[j] += hv[j];
    float4* hp = (float4*)&g_h[i * H];
#pragma unroll
    for (int q = 0; q < 8; q++)
        hp[q] = make_float4(hn[4*q], hn[4*q+1], hn[4*q+2], hn[4*q+3]);

    if (eW1n) {
        float Av[H], Bv[H];
#pragma unroll
        for (int j = 0; j < H; j++) { Av[j] = eb1n[j]; Bv[j] = 0.0f; }
#pragma unroll
        for (int k = 0; k < H; k++) {
            float v = hn[k];
            const float4* wa = (const float4*)&sEAt[k][0];
            const float4* wb = (const float4*)&sEBt[k][0];
#pragma unroll
            for (int q = 0; q < 8; q++) {
                float4 a = wa[q], b = wb[q];
                Av[4*q] += a.x*v; Av[4*q+1] += a.y*v; Av[4*q+2] += a.z*v; Av[4*q+3] += a.w*v;
                Bv[4*q] += b.x*v; Bv[4*q+1] += b.y*v; Bv[4*q+2] += b.z*v; Bv[4*q+3] += b.w*v;
            }
        }
        u32 pa[HQ], pb[HQ];
#pragma unroll
        for (int jq = 0; jq < HQ; jq++) {
            pa[jq] = b2u(__floats2bfloat162_rn(Av[2*jq], Av[2*jq+1]));
            pb[jq] = b2u(__floats2bfloat162_rn(Bv[2*jq], Bv[2*jq+1]));
        }
        uint4* Ao = (uint4*)&g_A[i * HQ];
        uint4* Bo = (uint4*)&g_B[i * HQ];
#pragma unroll
        for (int q = 0; q < 4; q++) {
            Ao[q] = make_uint4(pa[4*q], pa[4*q+1], pa[4*q+2], pa[4*q+3]);
            Bo[q] = make_uint4(pb[4*q], pb[4*q+1], pb[4*q+2], pb[4*q+3]);
        }
    }

    if (linW) {
#pragma unroll
        for (int c = 0; c < 3; c++) {
            float acc = 0.0f;
#pragma unroll
            for (int k = 0; k < DX; k++) acc += linW[c * DX + k] * xv[k];
            out[i * 3 + c] = acc;
        }
    }
}

extern "C" void kernel_launch(void* const* d_in, const int* in_sizes, int n_in,
                              void* d_out, int out_size)
{
    const float* node_attrs = (const float*)d_in[0];
    const float* positions  = (const float*)d_in[1];
    const int*   edge_index = (const int*)  d_in[2];
    const float* proj_W     = (const float*)d_in[3];
    const float* emb_in_W   = (const float*)d_in[4];
    const float* emb_in_b   = (const float*)d_in[5];
    const float* edge_W1    = (const float*)d_in[6];
    const float* edge_b1    = (const float*)d_in[7];
    const float* edge_W2    = (const float*)d_in[8];
    const float* edge_b2    = (const float*)d_in[9];
    const float* node_W1    = (const float*)d_in[10];
    const float* node_b1    = (const float*)d_in[11];
    const float* node_W2    = (const float*)d_in[12];
    const float* node_b2    = (const float*)d_in[13];
    const float* coord_W1   = (const float*)d_in[14];
    const float* coord_b1   = (const float*)d_in[15];
    const float* coord_W2   = (const float*)d_in[16];
    const float* lin_W      = (const float*)d_in[19];

    int n = in_sizes[0] / 3;
    int E = in_sizes[2] / 2;
    float* out = (float*)d_out;

    init_kernel<<<(n + 127) / 128, 128>>>(node_attrs, positions, proj_W,
                                          emb_in_W, emb_in_b, edge_W1, edge_b1, n); // 1
    hist_kernel<<<(E + 255) / 256, 256>>>(edge_index, E);                           // 2
    scan_kernel<<<1, SCAN_T>>>(n, E);                                               // 3
    scatter_kernel<<<(E + 255) / 256, 256>>>(edge_index, E);                        // 4
    nop_kernel<<<1, 32>>>();                                                        // 5

    int eblocks = (E + 2 * ETPB - 1) / (2 * ETPB);
    int nblocks = (n + NTPB - 1) / NTPB;

    for (int l = 0; l < 2; l++) {
        edge_kernel<<<eblocks, ETPB>>>(                                             // 6, 8
            E, positions,
            edge_W1 + l * H * 68,
            edge_W2 + l * H * H, edge_b2 + l * H,
            coord_W1 + l * H * H, coord_b1 + l * H,
            coord_W2 + l * H);
        node_kernel<<<nblocks, NTPB>>>(                                             // 7, 9
            node_W1 + l * H * 2 * H, node_b1 + l * H,
            node_W2 + l * H * H,     node_b2 + l * H,
            (l == 0) ? edge_W1 + H * 68 : nullptr,
            (l == 0) ? edge_b1 + H      : nullptr,
            (l == 1) ? lin_W            : nullptr,
            out, n);
    }
}

// round 14
// speedup vs baseline: 1.1475x; 1.1475x over previous
#include <cuda_runtime.h>
#include <cuda_bf16.h>

#define H    32
#define DX   16
#define HQ   16
#define NMAX 50048

typedef unsigned long long u64;
typedef unsigned int u32;
typedef __nv_bfloat162 bf2;

__device__ __align__(16) float g_x[NMAX * DX];
__device__ __align__(16) float g_h[NMAX * H];
__device__ __align__(16) u32 g_A[NMAX * HQ];
__device__ __align__(16) u32 g_B[NMAX * HQ];
__device__ __align__(16) float g_magg[NMAX * H];
__device__ __align__(16) float g_tagg[NMAX * DX];
__device__ float g_cnt[NMAX];
__device__ int g_dummy;

__device__ __forceinline__ float silu_f(float v) {
    return v * (1.0f / (1.0f + __expf(-v)));
}
__device__ __forceinline__ u32 b2u(bf2 v) { return *reinterpret_cast<u32*>(&v); }
__device__ __forceinline__ bf2 u2b(u32 v) { return *reinterpret_cast<bf2*>(&v); }

__device__ __forceinline__ bf2 silu_b(bf2 v) {
    bf2 h = __hmul2(v, __float2bfloat162_rn(0.5f));
    u32 tu;
    u32 hu = b2u(h);
    asm("tanh.approx.bf16x2 %0, %1;" : "=r"(tu) : "r"(hu));
    return __hmul2(h, __hadd2(u2b(tu), __float2bfloat162_rn(1.0f)));
}

__device__ __forceinline__ u64 pack2(float lo, float hi) {
    u64 r; asm("mov.b64 %0, {%1,%2};" : "=l"(r) : "f"(lo), "f"(hi)); return r;
}
__device__ __forceinline__ void unpack2(u64 v, float& lo, float& hi) {
    asm("mov.b64 {%0,%1}, %2;" : "=f"(lo), "=f"(hi) : "l"(v));
}
__device__ __forceinline__ void fma2(u64& d, u64 a, u64 b) {
    asm("fma.rn.f32x2 %0, %1, %2, %0;" : "+l"(d) : "l"(a), "l"(b));
}
__device__ __forceinline__ u64 dup2(float v) {
    u64 r; asm("mov.b64 %0, {%1,%1};" : "=l"(r) : "f"(v)); return r;
}
__device__ __forceinline__ void red_add_v4(float* a, float x, float y, float z, float w) {
    asm volatile("red.global.add.v4.f32 [%0], {%1,%2,%3,%4};"
                 :: "l"(a), "f"(x), "f"(y), "f"(z), "f"(w) : "memory");
}

// ---------------------------------------------------------------------------
__global__ __launch_bounds__(128, 4) void init_kernel(
    const float* __restrict__ attrs, const float* __restrict__ pos,
    const float* __restrict__ projW, const float* __restrict__ embW,
    const float* __restrict__ embB, const float* __restrict__ eW1,
    const float* __restrict__ eb1, int n)
{
    __shared__ __align__(16) float sWa[H][H];
    __shared__ __align__(16) float sWb[H][H];
    for (int idx = threadIdx.x; idx < H * H; idx += 128) {
        int j = idx >> 5, k = idx & 31;
        sWa[k][j] = eW1[j * 68 + k];
        sWb[k][j] = eW1[j * 68 + 32 + k];
    }
    __syncthreads();
    int i = blockIdx.x * 128 + threadIdx.x;
    if (i >= n) return;

    float p0 = pos[i*3], p1 = pos[i*3+1], p2 = pos[i*3+2];
    float xv[DX];
#pragma unroll
    for (int j = 0; j < DX; j++)
        xv[j] = projW[j*3]*p0 + projW[j*3+1]*p1 + projW[j*3+2]*p2;
    float4* xo = (float4*)&g_x[i * DX];
#pragma unroll
    for (int q = 0; q < 4; q++)
        xo[q] = make_float4(xv[4*q], xv[4*q+1], xv[4*q+2], xv[4*q+3]);

    float a0 = attrs[i*3], a1 = attrs[i*3+1], a2 = attrs[i*3+2];
    float hv[H];
#pragma unroll
    for (int j = 0; j < H; j++)
        hv[j] = embW[j*3]*a0 + embW[j*3+1]*a1 + embW[j*3+2]*a2 + embB[j];
    float4* ho = (float4*)&g_h[i * H];
#pragma unroll
    for (int q = 0; q < 8; q++)
        ho[q] = make_float4(hv[4*q], hv[4*q+1], hv[4*q+2], hv[4*q+3]);

    float Av[H], Bv[H];
#pragma unroll
    for (int j = 0; j < H; j++) { Av[j] = eb1[j]; Bv[j] = 0.0f; }
#pragma unroll
    for (int k = 0; k < H; k++) {
        float hk = hv[k];
        const float4* wa = (const float4*)&sWa[k][0];
        const float4* wb = (const float4*)&sWb[k][0];
#pragma unroll
        for (int q = 0; q < 8; q++) {
            float4 a = wa[q], b = wb[q];
            Av[4*q] += a.x*hk; Av[4*q+1] += a.y*hk; Av[4*q+2] += a.z*hk; Av[4*q+3] += a.w*hk;
            Bv[4*q] += b.x*hk; Bv[4*q+1] += b.y*hk; Bv[4*q+2] += b.z*hk; Bv[4*q+3] += b.w*hk;
        }
    }
    u32 pa[HQ], pb[HQ];
#pragma unroll
    for (int jq = 0; jq < HQ; jq++) {
        pa[jq] = b2u(__floats2bfloat162_rn(Av[2*jq], Av[2*jq+1]));
        pb[jq] = b2u(__floats2bfloat162_rn(Bv[2*jq], Bv[2*jq+1]));
    }
    uint4* Ao = (uint4*)&g_A[i * HQ];
    uint4* Bo = (uint4*)&g_B[i * HQ];
#pragma unroll
    for (int q = 0; q < 4; q++) {
        Ao[q] = make_uint4(pa[4*q], pa[4*q+1], pa[4*q+2], pa[4*q+3]);
        Bo[q] = make_uint4(pb[4*q], pb[4*q+1], pb[4*q+2], pb[4*q+3]);
    }

    const float4 z4 = make_float4(0.f, 0.f, 0.f, 0.f);
    float4* mz = (float4*)&g_magg[i * H];
    float4* tz = (float4*)&g_tagg[i * DX];
#pragma unroll
    for (int q = 0; q < 8; q++) mz[q] = z4;
#pragma unroll
    for (int q = 0; q < 4; q++) tz[q] = z4;
    g_cnt[i] = 0.0f;
}

__global__ void count_kernel(const int* __restrict__ ei, int E)
{
    int e = blockIdx.x * blockDim.x + threadIdx.x;
    if (e < E) atomicAdd(&g_cnt[ei[e]], 1.0f);
}

__global__ void nop_kernel() { if (blockIdx.x == 1u << 30) g_dummy = 1; }

// ---------------------------------------------------------------------------
// edge kernel: T=3 edges/thread, bf16 MLP, shared weight LDS across edges
// ---------------------------------------------------------------------------
#define ETPB 128
#define T    3

__global__ __launch_bounds__(ETPB, 2) void edge_kernel(
    const int* __restrict__ ei, int E,
    const float* __restrict__ pos,
    const float* __restrict__ W1,
    const float* __restrict__ W2,
    const float* __restrict__ b2,
    const float* __restrict__ cW1,
    const float* __restrict__ cb1,
    const float* __restrict__ cW2)
{
    __shared__ __align__(16) u32 s_W2t[H][HQ];
    __shared__ __align__(16) u32 s_cW1t[H][HQ];
    __shared__ __align__(16) u64 s_wr2[HQ];
    __shared__ __align__(16) u64 s_we2[3][HQ];
    __shared__ u32 s_b2b[HQ], s_cb1b[HQ], s_cw2b[HQ];

    for (int idx = threadIdx.x; idx < H * HQ; idx += ETPB) {
        int k = idx >> 4, jq = idx & 15;
        s_W2t[k][jq]  = b2u(__floats2bfloat162_rn(W2[(2*jq)*H+k],  W2[(2*jq+1)*H+k]));
        s_cW1t[k][jq] = b2u(__floats2bfloat162_rn(cW1[(2*jq)*H+k], cW1[(2*jq+1)*H+k]));
    }
    if (threadIdx.x < HQ) {
        int jq = threadIdx.x;
        s_wr2[jq]    = pack2(W1[(2*jq)*68+64], W1[(2*jq+1)*68+64]);
        s_we2[0][jq] = pack2(W1[(2*jq)*68+65], W1[(2*jq+1)*68+65]);
        s_we2[1][jq] = pack2(W1[(2*jq)*68+66], W1[(2*jq+1)*68+66]);
        s_we2[2][jq] = pack2(W1[(2*jq)*68+67], W1[(2*jq+1)*68+67]);
        s_b2b[jq]  = b2u(__floats2bfloat162_rn(b2[2*jq],  b2[2*jq+1]));
        s_cb1b[jq] = b2u(__floats2bfloat162_rn(cb1[2*jq], cb1[2*jq+1]));
        s_cw2b[jq] = b2u(__floats2bfloat162_rn(cW2[2*jq], cW2[2*jq+1]));
    }
    __syncthreads();

    int ebase = blockIdx.x * (T * ETPB) + threadIdx.x;
    if (ebase >= E) return;

    int eidx[T], row[T], col[T];
    bool valid[T];
#pragma unroll
    for (int t = 0; t < T; t++) {
        int e = ebase + t * ETPB;
        valid[t] = (e < E);
        eidx[t] = valid[t] ? e : ebase;
        row[t] = ei[eidx[t]];
        col[t] = ei[E + eidx[t]];
    }

    float ea[T][3];
    bf2 cd[T][8];
    float rad[T];
#pragma unroll
    for (int t = 0; t < T; t++) {
        ea[t][0] = pos[row[t]*3]   - pos[col[t]*3];
        ea[t][1] = pos[row[t]*3+1] - pos[col[t]*3+1];
        ea[t][2] = pos[row[t]*3+2] - pos[col[t]*3+2];
        const float4* xr = (const float4*)&g_x[row[t] * DX];
        const float4* xc = (const float4*)&g_x[col[t] * DX];
        float r = 0.0f;
#pragma unroll
        for (int q = 0; q < 4; q++) {
            float4 a = xr[q], b = xc[q];
            float d0 = a.x-b.x, d1 = a.y-b.y, d2 = a.z-b.z, d3 = a.w-b.w;
            cd[t][2*q]   = __floats2bfloat162_rn(d0, d1);
            cd[t][2*q+1] = __floats2bfloat162_rn(d2, d3);
            r += d0*d0 + d1*d1 + d2*d2 + d3*d3;
        }
        rad[t] = r;
    }

    // layer 1 per edge (transient f32x2 accumulators)
    bf2 abf[T][HQ];
#pragma unroll
    for (int t = 0; t < T; t++) {
        u64 acc2[HQ];
        const uint4* Ar = (const uint4*)&g_A[row[t] * HQ];
        const uint4* Bc = (const uint4*)&g_B[col[t] * HQ];
#pragma unroll
        for (int q = 0; q < 4; q++) {
            uint4 a4 = Ar[q], b4 = Bc[q];
            const u32* ap = (const u32*)&a4;
            const u32* bp = (const u32*)&b4;
#pragma unroll
            for (int r = 0; r < 4; r++) {
                float2 af = __bfloat1622float2(u2b(ap[r]));
                float2 bf = __bfloat1622float2(u2b(bp[r]));
                acc2[4*q + r] = pack2(af.x + bf.x, af.y + bf.y);
            }
        }
        u64 rad2 = dup2(rad[t]);
        u64 e02 = dup2(ea[t][0]), e12 = dup2(ea[t][1]), e22 = dup2(ea[t][2]);
#pragma unroll
        for (int jq = 0; jq < HQ; jq++) {
            fma2(acc2[jq], s_wr2[jq], rad2);
            fma2(acc2[jq], s_we2[0][jq], e02);
            fma2(acc2[jq], s_we2[1][jq], e12);
            fma2(acc2[jq], s_we2[2][jq], e22);
        }
#pragma unroll
        for (int jq = 0; jq < HQ; jq++) {
            float lo, hi;
            unpack2(acc2[jq], lo, hi);
            abf[t][jq] = silu_b(__floats2bfloat162_rn(lo, hi));
        }
    }

    // layer 2: shared weight loads across T edges
    bf2 ms[T][HQ];
    {
        bf2 m2[T][HQ];
#pragma unroll
        for (int t = 0; t < T; t++)
#pragma unroll
            for (int jq = 0; jq < HQ; jq++) m2[t][jq] = u2b(s_b2b[jq]);
#pragma unroll
        for (int k = 0; k < H; k++) {
            bf2 mk[T];
#pragma unroll
            for (int t = 0; t < T; t++)
                mk[t] = (k & 1) ? __high2bfloat162(abf[t][k >> 1]) : __low2bfloat162(abf[t][k >> 1]);
            const uint4* w4 = (const uint4*)&s_W2t[k][0];
#pragma unroll
            for (int q = 0; q < 4; q++) {
                uint4 w = w4[q];
#pragma unroll
                for (int t = 0; t < T; t++) {
                    m2[t][4*q]   = __hfma2(u2b(w.x), mk[t], m2[t][4*q]);
                    m2[t][4*q+1] = __hfma2(u2b(w.y), mk[t], m2[t][4*q+1]);
                    m2[t][4*q+2] = __hfma2(u2b(w.z), mk[t], m2[t][4*q+2]);
                    m2[t][4*q+3] = __hfma2(u2b(w.w), mk[t], m2[t][4*q+3]);
                }
            }
        }
#pragma unroll
        for (int t = 0; t < T; t++)
#pragma unroll
            for (int jq = 0; jq < HQ; jq++) ms[t][jq] = silu_b(m2[t][jq]);
    }

    // coord head: shared weight loads across T edges
    float cm[T];
    {
        bf2 c2[T][HQ];
#pragma unroll
        for (int t = 0; t < T; t++)
#pragma unroll
            for (int jq = 0; jq < HQ; jq++) c2[t][jq] = u2b(s_cb1b[jq]);
#pragma unroll
        for (int k = 0; k < H; k++) {
            bf2 mk[T];
#pragma unroll
            for (int t = 0; t < T; t++)
                mk[t] = (k & 1) ? __high2bfloat162(ms[t][k >> 1]) : __low2bfloat162(ms[t][k >> 1]);
            const uint4* w4 = (const uint4*)&s_cW1t[k][0];
#pragma unroll
            for (int q = 0; q < 4; q++) {
                uint4 w = w4[q];
#pragma unroll
                for (int t = 0; t < T; t++) {
                    c2[t][4*q]   = __hfma2(u2b(w.x), mk[t], c2[t][4*q]);
                    c2[t][4*q+1] = __hfma2(u2b(w.y), mk[t], c2[t][4*q+1]);
                    c2[t][4*q+2] = __hfma2(u2b(w.z), mk[t], c2[t][4*q+2]);
                    c2[t][4*q+3] = __hfma2(u2b(w.w), mk[t], c2[t][4*q+3]);
                }
            }
        }
#pragma unroll
        for (int t = 0; t < T; t++) {
            float acc = 0.0f;
#pragma unroll
            for (int jq = 0; jq < HQ; jq++) {
                bf2 p = __hmul2(u2b(s_cw2b[jq]), silu_b(c2[t][jq]));
                float2 pf = __bfloat1622float2(p);
                acc += pf.x + pf.y;
            }
            cm[t] = acc;
        }
    }

    // scatters
#pragma unroll
    for (int t = 0; t < T; t++) {
        if (!valid[t]) continue;
        float* mago = &g_magg[row[t] * H];
#pragma unroll
        for (int q = 0; q < 8; q++) {
            float2 f0 = __bfloat1622float2(ms[t][2*q]);
            float2 f1 = __bfloat1622float2(ms[t][2*q+1]);
            red_add_v4(mago + 4*q, f0.x, f0.y, f1.x, f1.y);
        }
        float* tago = &g_tagg[row[t] * DX];
#pragma unroll
        for (int q = 0; q < 4; q++) {
            float2 d0 = __bfloat1622float2(cd[t][2*q]);
            float2 d1 = __bfloat1622float2(cd[t][2*q+1]);
            red_add_v4(tago + 4*q, d0.x*cm[t], d0.y*cm[t], d1.x*cm[t], d1.y*cm[t]);
        }
    }
}

// ---------------------------------------------------------------------------
#define NTPB 128

__global__ __launch_bounds__(NTPB, 4) void node_kernel(
    const float* __restrict__ nW1, const float* __restrict__ nb1,
    const float* __restrict__ nW2, const float* __restrict__ nb2,
    const float* __restrict__ eW1n, const float* __restrict__ eb1n,
    const float* __restrict__ linW, float* __restrict__ out, int n)
{
    __shared__ __align__(16) float sN1t[2 * H][H];
    __shared__ __align__(16) float sN2t[H][H];
    __shared__ __align__(16) float sEAt[H][H];
    __shared__ __align__(16) float sEBt[H][H];

    int i = blockIdx.x * NTPB + threadIdx.x;
    bool active = (i < n);

    float cnt = 0.f;
    float4 xr[4], tr[4], hr[8], mr[8];
    if (active) {
        cnt = g_cnt[i];
        const float4* xp = (const float4*)&g_x[i * DX];
        const float4* tp = (const float4*)&g_tagg[i * DX];
        const float4* hp = (const float4*)&g_h[i * H];
        const float4* mp = (const float4*)&g_magg[i * H];
#pragma unroll
        for (int q = 0; q < 4; q++) { xr[q] = xp[q]; tr[q] = tp[q]; }
#pragma unroll
        for (int q = 0; q < 8; q++) { hr[q] = hp[q]; mr[q] = mp[q]; }
    }

    for (int idx = threadIdx.x; idx < H * 2 * H; idx += NTPB) {
        int j = idx >> 6, k = idx & 63;
        sN1t[k][j] = nW1[idx];
    }
    for (int idx = threadIdx.x; idx < H * H; idx += NTPB) {
        int j = idx >> 5, k = idx & 31;
        sN2t[k][j] = nW2[idx];
        if (eW1n) {
            sEAt[k][j] = eW1n[j * 68 + k];
            sEBt[k][j] = eW1n[j * 68 + 32 + k];
        }
    }
    __syncthreads();

    if (!active) return;

    float inv = 1.0f / fmaxf(cnt, 1.0f);
    const float4 z4 = make_float4(0.f, 0.f, 0.f, 0.f);

    float xv[DX];
    float4* xp = (float4*)&g_x[i * DX];
    float4* tp = (float4*)&g_tagg[i * DX];
#pragma unroll
    for (int q = 0; q < 4; q++) {
        xv[4*q]   = xr[q].x + tr[q].x * inv;
        xv[4*q+1] = xr[q].y + tr[q].y * inv;
        xv[4*q+2] = xr[q].z + tr[q].z * inv;
        xv[4*q+3] = xr[q].w + tr[q].w * inv;
        xp[q] = make_float4(xv[4*q], xv[4*q+1], xv[4*q+2], xv[4*q+3]);
        tp[q] = z4;
    }

    float hv[H], mg[H];
    float4* mp = (float4*)&g_magg[i * H];
#pragma unroll
    for (int q = 0; q < 8; q++) {
        hv[4*q] = hr[q].x; hv[4*q+1] = hr[q].y; hv[4*q+2] = hr[q].z; hv[4*q+3] = hr[q].w;
        mg[4*q] = mr[q].x; mg[4*q+1] = mr[q].y; mg[4*q+2] = mr[q].z; mg[4*q+3] = mr[q].w;
        mp[q] = z4;
    }

    float u[H];
#pragma unroll
    for (int j = 0; j < H; j++) u[j] = nb1[j];
#pragma unroll
    for (int k = 0; k < H; k++) {
        float v = hv[k];
        const float4* w4 = (const float4*)&sN1t[k][0];
#pragma unroll
        for (int q = 0; q < 8; q++) {
            float4 w = w4[q];
            u[4*q] += w.x*v; u[4*q+1] += w.y*v; u[4*q+2] += w.z*v; u[4*q+3] += w.w*v;
        }
    }
#pragma unroll
    for (int k = 0; k < H; k++) {
        float v = mg[k];
        const float4* w4 = (const float4*)&sN1t[H + k][0];
#pragma unroll
        for (int q = 0; q < 8; q++) {
            float4 w = w4[q];
            u[4*q] += w.x*v; u[4*q+1] += w.y*v; u[4*q+2] += w.z*v; u[4*q+3] += w.w*v;
        }
    }
#pragma unroll
    for (int j = 0; j < H; j++) u[j] = silu_f(u[j]);

    float hn[H];
#pragma unroll
    for (int j = 0; j < H; j++) hn[j] = nb2[j];
#pragma unroll
    for (int k = 0; k < H; k++) {
        float v = u[k];
        const float4* w4 = (const float4*)&sN2t[k][0];
#pragma unroll
        for (int q = 0; q < 8; q++) {
            float4 w = w4[q];
            hn[4*q] += w.x*v; hn[4*q+1] += w.y*v; hn[4*q+2] += w.z*v; hn[4*q+3] += w.w*v;
        }
    }
#pragma unroll
    for (int j = 0; j < H; j++) hn[j] += hv[j];
    float4* hp = (float4*)&g_h[i * H];
#pragma unroll
    for (int q = 0; q < 8; q++)
        hp[q] = make_float4(hn[4*q], hn[4*q+1], hn[4*q+2], hn[4*q+3]);

    if (eW1n) {
        float Av[H], Bv[H];
#pragma unroll
        for (int j = 0; j < H; j++) { Av[j] = eb1n[j]; Bv[j] = 0.0f; }
#pragma unroll
        for (int k = 0; k < H; k++) {
            float v = hn[k];
            const float4* wa = (const float4*)&sEAt[k][0];
            const float4* wb = (const float4*)&sEBt[k][0];
#pragma unroll
            for (int q = 0; q < 8; q++) {
                float4 a = wa[q], b = wb[q];
                Av[4*q] += a.x*v; Av[4*q+1] += a.y*v; Av[4*q+2] += a.z*v; Av[4*q+3] += a.w*v;
                Bv[4*q] += b.x*v; Bv[4*q+1] += b.y*v; Bv[4*q+2] += b.z*v; Bv[4*q+3] += b.w*v;
            }
        }
        u32 pa[HQ], pb[HQ];
#pragma unroll
        for (int jq = 0; jq < HQ; jq++) {
            pa[jq] = b2u(__floats2bfloat162_rn(Av[2*jq], Av[2*jq+1]));
            pb[jq] = b2u(__floats2bfloat162_rn(Bv[2*jq], Bv[2*jq+1]));
        }
        uint4* Ao = (uint4*)&g_A[i * HQ];
        uint4* Bo = (uint4*)&g_B[i * HQ];
#pragma unroll
        for (int q = 0; q < 4; q++) {
            Ao[q] = make_uint4(pa[4*q], pa[4*q+1], pa[4*q+2], pa[4*q+3]);
            Bo[q] = make_uint4(pb[4*q], pb[4*q+1], pb[4*q+2], pb[4*q+3]);
        }
    }

    if (linW) {
#pragma unroll
        for (int c = 0; c < 3; c++) {
            float acc = 0.0f;
#pragma unroll
            for (int k = 0; k < DX; k++) acc += linW[c * DX + k] * xv[k];
            out[i * 3 + c] = acc;
        }
    }
}

extern "C" void kernel_launch(void* const* d_in, const int* in_sizes, int n_in,
                              void* d_out, int out_size)
{
    const float* node_attrs = (const float*)d_in[0];
    const float* positions  = (const float*)d_in[1];
    const int*   edge_index = (const int*)  d_in[2];
    const float* proj_W     = (const float*)d_in[3];
    const float* emb_in_W   = (const float*)d_in[4];
    const float* emb_in_b   = (const float*)d_in[5];
    const float* edge_W1    = (const float*)d_in[6];
    const float* edge_b1    = (const float*)d_in[7];
    const float* edge_W2    = (const float*)d_in[8];
    const float* edge_b2    = (const float*)d_in[9];
    const float* node_W1    = (const float*)d_in[10];
    const float* node_b1    = (const float*)d_in[11];
    const float* node_W2    = (const float*)d_in[12];
    const float* node_b2    = (const float*)d_in[13];
    const float* coord_W1   = (const float*)d_in[14];
    const float* coord_b1   = (const float*)d_in[15];
    const float* coord_W2   = (const float*)d_in[16];
    const float* lin_W      = (const float*)d_in[19];

    int n = in_sizes[0] / 3;
    int E = in_sizes[2] / 2;
    float* out = (float*)d_out;

    init_kernel<<<(n + 127) / 128, 128>>>(node_attrs, positions, proj_W,
                                          emb_in_W, emb_in_b, edge_W1, edge_b1, n);
    count_kernel<<<(E + 255) / 256, 256>>>(edge_index, E);
    nop_kernel<<<1, 32>>>();

    int eblocks = (E + T * ETPB - 1) / (T * ETPB);
    int nblocks = (n + NTPB - 1) / NTPB;

    for (int l = 0; l < 2; l++) {
        edge_kernel<<<eblocks, ETPB>>>(
            edge_index, E, positions,
            edge_W1 + l * H * 68,
            edge_W2 + l * H * H, edge_b2 + l * H,
            coord_W1 + l * H * H, coord_b1 + l * H,
            coord_W2 + l * H);
        node_kernel<<<nblocks, NTPB>>>(
            node_W1 + l * H * 2 * H, node_b1 + l * H,
            node_W2 + l * H * H,     node_b2 + l * H,
            (l == 0) ? edge_W1 + H * 68 : nullptr,
            (l == 0) ? edge_b1 + H      : nullptr,
            (l == 1) ? lin_W            : nullptr,
            out, n);
    }
}

// round 15
// speedup vs baseline: 1.5910x; 1.3864x over previous
#include <cuda_runtime.h>
#include <cuda_bf16.h>

#define H    32
#define DX   16
#define HQ   16
#define NMAX 50048

typedef unsigned long long u64;
typedef unsigned int u32;
typedef __nv_bfloat162 bf2;

__device__ __align__(16) float g_x[NMAX * DX];
__device__ __align__(16) float g_h[NMAX * H];
__device__ __align__(16) u32 g_A[NMAX * HQ];
__device__ __align__(16) u32 g_B[NMAX * HQ];
__device__ __align__(16) float g_magg[NMAX * H];
__device__ __align__(16) float g_tagg[NMAX * DX];
__device__ float g_cnt[NMAX];
__device__ int g_dummy;

__device__ __forceinline__ float silu_f(float v) {
    return v * (1.0f / (1.0f + __expf(-v)));
}
__device__ __forceinline__ u32 b2u(bf2 v) { return *reinterpret_cast<u32*>(&v); }
__device__ __forceinline__ bf2 u2b(u32 v) { return *reinterpret_cast<bf2*>(&v); }

__device__ __forceinline__ bf2 silu_b(bf2 v) {
    bf2 h = __hmul2(v, __float2bfloat162_rn(0.5f));
    u32 tu;
    u32 hu = b2u(h);
    asm("tanh.approx.bf16x2 %0, %1;" : "=r"(tu) : "r"(hu));
    return __hmul2(h, __hadd2(u2b(tu), __float2bfloat162_rn(1.0f)));
}

// pack two f32 into bf16x2 (lo first)
__device__ __forceinline__ u32 packf(float lo, float hi) {
    u32 r; asm("cvt.rn.bf16x2.f32 %0, %1, %2;" : "=r"(r) : "f"(hi), "f"(lo)); return r;
}

__device__ __forceinline__ void mma16816(float& c0, float& c1, float& c2, float& c3,
                                         u32 a0, u32 a1, u32 a2, u32 a3, u32 b0, u32 b1) {
    asm("mma.sync.aligned.m16n8k16.row.col.f32.bf16.bf16.f32 "
        "{%0,%1,%2,%3},{%4,%5,%6,%7},{%8,%9},{%0,%1,%2,%3};"
        : "+f"(c0), "+f"(c1), "+f"(c2), "+f"(c3)
        : "r"(a0), "r"(a1), "r"(a2), "r"(a3), "r"(b0), "r"(b1));
}

__device__ __forceinline__ void red_add_v4(float* a, float x, float y, float z, float w) {
    asm volatile("red.global.add.v4.f32 [%0], {%1,%2,%3,%4};"
                 :: "l"(a), "f"(x), "f"(y), "f"(z), "f"(w) : "memory");
}
__device__ __forceinline__ void red_add_v2(float* a, float x, float y) {
    asm volatile("red.global.add.v2.f32 [%0], {%1,%2};"
                 :: "l"(a), "f"(x), "f"(y) : "memory");
}

// ---------------------------------------------------------------------------
__global__ __launch_bounds__(128, 4) void init_kernel(
    const float* __restrict__ attrs, const float* __restrict__ pos,
    const float* __restrict__ projW, const float* __restrict__ embW,
    const float* __restrict__ embB, const float* __restrict__ eW1,
    const float* __restrict__ eb1, int n)
{
    __shared__ __align__(16) float sWa[H][H];
    __shared__ __align__(16) float sWb[H][H];
    for (int idx = threadIdx.x; idx < H * H; idx += 128) {
        int j = idx >> 5, k = idx & 31;
        sWa[k][j] = eW1[j * 68 + k];
        sWb[k][j] = eW1[j * 68 + 32 + k];
    }
    __syncthreads();
    int i = blockIdx.x * 128 + threadIdx.x;
    if (i >= n) return;

    float p0 = pos[i*3], p1 = pos[i*3+1], p2 = pos[i*3+2];
    float xv[DX];
#pragma unroll
    for (int j = 0; j < DX; j++)
        xv[j] = projW[j*3]*p0 + projW[j*3+1]*p1 + projW[j*3+2]*p2;
    float4* xo = (float4*)&g_x[i * DX];
#pragma unroll
    for (int q = 0; q < 4; q++)
        xo[q] = make_float4(xv[4*q], xv[4*q+1], xv[4*q+2], xv[4*q+3]);

    float a0 = attrs[i*3], a1 = attrs[i*3+1], a2 = attrs[i*3+2];
    float hv[H];
#pragma unroll
    for (int j = 0; j < H; j++)
        hv[j] = embW[j*3]*a0 + embW[j*3+1]*a1 + embW[j*3+2]*a2 + embB[j];
    float4* ho = (float4*)&g_h[i * H];
#pragma unroll
    for (int q = 0; q < 8; q++)
        ho[q] = make_float4(hv[4*q], hv[4*q+1], hv[4*q+2], hv[4*q+3]);

    float Av[H], Bv[H];
#pragma unroll
    for (int j = 0; j < H; j++) { Av[j] = eb1[j]; Bv[j] = 0.0f; }
#pragma unroll
    for (int k = 0; k < H; k++) {
        float hk = hv[k];
        const float4* wa = (const float4*)&sWa[k][0];
        const float4* wb = (const float4*)&sWb[k][0];
#pragma unroll
        for (int q = 0; q < 8; q++) {
            float4 a = wa[q], b = wb[q];
            Av[4*q] += a.x*hk; Av[4*q+1] += a.y*hk; Av[4*q+2] += a.z*hk; Av[4*q+3] += a.w*hk;
            Bv[4*q] += b.x*hk; Bv[4*q+1] += b.y*hk; Bv[4*q+2] += b.z*hk; Bv[4*q+3] += b.w*hk;
        }
    }
    u32 pa[HQ], pb[HQ];
#pragma unroll
    for (int jq = 0; jq < HQ; jq++) {
        pa[jq] = packf(Av[2*jq], Av[2*jq+1]);
        pb[jq] = packf(Bv[2*jq], Bv[2*jq+1]);
    }
    uint4* Ao = (uint4*)&g_A[i * HQ];
    uint4* Bo = (uint4*)&g_B[i * HQ];
#pragma unroll
    for (int q = 0; q < 4; q++) {
        Ao[q] = make_uint4(pa[4*q], pa[4*q+1], pa[4*q+2], pa[4*q+3]);
        Bo[q] = make_uint4(pb[4*q], pb[4*q+1], pb[4*q+2], pb[4*q+3]);
    }

    const float4 z4 = make_float4(0.f, 0.f, 0.f, 0.f);
    float4* mz = (float4*)&g_magg[i * H];
    float4* tz = (float4*)&g_tagg[i * DX];
#pragma unroll
    for (int q = 0; q < 8; q++) mz[q] = z4;
#pragma unroll
    for (int q = 0; q < 4; q++) tz[q] = z4;
    g_cnt[i] = 0.0f;
}

__global__ void count_kernel(const int* __restrict__ ei, int E)
{
    int e = blockIdx.x * blockDim.x + threadIdx.x;
    if (e < E) atomicAdd(&g_cnt[ei[e]], 1.0f);
}

__global__ void nop_kernel() { if (blockIdx.x == 1u << 30) g_dummy = 1; }

// ---------------------------------------------------------------------------
// edge kernel: warp = 32 edges; all three GEMVs via mma.sync bf16 with
// register-resident weight fragments and in-register C->A conversion.
// ---------------------------------------------------------------------------
#define EBLK 128
#define SSTR 80   // staged-activation row stride (64B data + 16B pad)

__global__ __launch_bounds__(EBLK) void edge_kernel(
    const int* __restrict__ ei, int E,
    const float* __restrict__ pos,
    const float* __restrict__ W1,   // [32][68], cols 64..67 = geo coeffs
    const float* __restrict__ W2,   // [32][32]
    const float* __restrict__ b2,
    const float* __restrict__ cW1,  // [32][32]
    const float* __restrict__ cb1,
    const float* __restrict__ cW2)  // [32]
{
    __shared__ __align__(16) unsigned char sS[4][32 * SSTR];
    __shared__ __align__(8)  u32 sG[4][32 * 2];
    __shared__ int sRow[4][32];

    int tid = threadIdx.x, wid = tid >> 5, lane = tid & 31;
    int g = lane >> 2, t = lane & 3;

    // ---- one-time register weight fragments --------------------------------
    u32 WB[2][4][2], CB[2][4][2], GB[4];
    float B2c0[4], B2c1[4], CB1c0[4], CB1c1[4];
    u32 CW2p[4];
#pragma unroll
    for (int nt = 0; nt < 4; nt++) {
        int j = 8 * nt + g;
#pragma unroll
        for (int kt = 0; kt < 2; kt++) {
            int k0 = 16 * kt + 2 * t;
            WB[kt][nt][0] = packf(W2[j*H + k0],     W2[j*H + k0 + 1]);
            WB[kt][nt][1] = packf(W2[j*H + k0 + 8], W2[j*H + k0 + 9]);
            CB[kt][nt][0] = packf(cW1[j*H + k0],     cW1[j*H + k0 + 1]);
            CB[kt][nt][1] = packf(cW1[j*H + k0 + 8], cW1[j*H + k0 + 9]);
        }
        float glo = 0.f, ghi = 0.f;
        if (t == 0) { glo = W1[j*68 + 64]; ghi = W1[j*68 + 65]; }
        else if (t == 1) { glo = W1[j*68 + 66]; ghi = W1[j*68 + 67]; }
        GB[nt] = packf(glo, ghi);

        int jc = 8 * nt + 2 * t;
        B2c0[nt]  = b2[jc];   B2c1[nt]  = b2[jc + 1];
        CB1c0[nt] = cb1[jc];  CB1c1[nt] = cb1[jc + 1];
        CW2p[nt]  = packf(cW2[jc], cW2[jc + 1]);
    }

    unsigned char* mS = &sS[wid][0];
    u32* mG = &sG[wid][0];
    int* mR = &sRow[wid][0];

    int warps_total = gridDim.x * (EBLK / 32);
    int wgl = blockIdx.x * (EBLK / 32) + wid;

    for (int base = wgl * 32; base < E; base += warps_total * 32) {
        int e = base + lane;
        bool vme = (e < E);
        int ec = vme ? e : (E - 1);
        int row = ei[ec], col = ei[E + ec];
        mR[lane] = row;

        float ea0 = pos[row*3]   - pos[col*3];
        float ea1 = pos[row*3+1] - pos[col*3+1];
        float ea2 = pos[row*3+2] - pos[col*3+2];

        bf2 cd[8];
        float radial = 0.0f;
        {
            const float4* xr = (const float4*)&g_x[row * DX];
            const float4* xc = (const float4*)&g_x[col * DX];
#pragma unroll
            for (int q = 0; q < 4; q++) {
                float4 a = xr[q], b = xc[q];
                float d0 = a.x-b.x, d1 = a.y-b.y, d2 = a.z-b.z, d3 = a.w-b.w;
                cd[2*q]   = u2b(packf(d0, d1));
                cd[2*q+1] = u2b(packf(d2, d3));
                radial += d0*d0 + d1*d1 + d2*d2 + d3*d3;
            }
        }

        // stage geo and A[row]+B[col] sums
        mG[lane*2 + 0] = packf(radial, ea0);
        mG[lane*2 + 1] = packf(ea1, ea2);
        {
            const uint4* Ar = (const uint4*)&g_A[row * HQ];
            const uint4* Bc = (const uint4*)&g_B[col * HQ];
            uint4* dst = (uint4*)&mS[lane * SSTR];
#pragma unroll
            for (int q = 0; q < 4; q++) {
                uint4 a4 = Ar[q], b4 = Bc[q];
                uint4 o;
                o.x = b2u(__hadd2(u2b(a4.x), u2b(b4.x)));
                o.y = b2u(__hadd2(u2b(a4.y), u2b(b4.y)));
                o.z = b2u(__hadd2(u2b(a4.z), u2b(b4.z)));
                o.w = b2u(__hadd2(u2b(a4.w), u2b(b4.w)));
                dst[q] = o;
            }
        }
        __syncwarp();

        // ---- layer 1: C init from staged sums + geo mma, silu -> msm ----
        bf2 msm[2][4][2];
#pragma unroll
        for (int mt = 0; mt < 2; mt++) {
            u32 ga0 = 0, ga1 = 0;
            if (t < 2) {
                ga0 = mG[(mt*16 + g) * 2 + t];
                ga1 = mG[(mt*16 + g + 8) * 2 + t];
            }
#pragma unroll
            for (int nt = 0; nt < 4; nt++) {
                u32 s0 = *(const u32*)&mS[(mt*16 + g) * SSTR + 16*nt + 4*t];
                u32 s1 = *(const u32*)&mS[(mt*16 + g + 8) * SSTR + 16*nt + 4*t];
                float2 f0 = __bfloat1622float2(u2b(s0));
                float2 f1 = __bfloat1622float2(u2b(s1));
                float c0 = f0.x, c1 = f0.y, c2 = f1.x, c3 = f1.y;
                mma16816(c0, c1, c2, c3, ga0, ga1, 0u, 0u, GB[nt], 0u);
                msm[mt][nt][0] = silu_b(u2b(packf(c0, c1)));
                msm[mt][nt][1] = silu_b(u2b(packf(c2, c3)));
            }
        }

        // ---- layer 2: C->A identity, mma, silu -> out2 (= messages m) ----
        bf2 out2[2][4][2];
#pragma unroll
        for (int mt = 0; mt < 2; mt++) {
            u32 A0[2][4];
#pragma unroll
            for (int kt = 0; kt < 2; kt++) {
                A0[kt][0] = b2u(msm[mt][2*kt][0]);
                A0[kt][1] = b2u(msm[mt][2*kt][1]);
                A0[kt][2] = b2u(msm[mt][2*kt+1][0]);
                A0[kt][3] = b2u(msm[mt][2*kt+1][1]);
            }
#pragma unroll
            for (int nt = 0; nt < 4; nt++) {
                float c0 = B2c0[nt], c1 = B2c1[nt], c2 = B2c0[nt], c3 = B2c1[nt];
                mma16816(c0, c1, c2, c3, A0[0][0], A0[0][1], A0[0][2], A0[0][3],
                         WB[0][nt][0], WB[0][nt][1]);
                mma16816(c0, c1, c2, c3, A0[1][0], A0[1][1], A0[1][2], A0[1][3],
                         WB[1][nt][0], WB[1][nt][1]);
                out2[mt][nt][0] = silu_b(u2b(packf(c0, c1)));
                out2[mt][nt][1] = silu_b(u2b(packf(c2, c3)));
            }
        }

        // ---- coord head: same identity, silu, dot with cW2 -> cm ----------
        float pl[4];
#pragma unroll
        for (int mt = 0; mt < 2; mt++) {
            u32 A0[2][4];
#pragma unroll
            for (int kt = 0; kt < 2; kt++) {
                A0[kt][0] = b2u(out2[mt][2*kt][0]);
                A0[kt][1] = b2u(out2[mt][2*kt][1]);
                A0[kt][2] = b2u(out2[mt][2*kt+1][0]);
                A0[kt][3] = b2u(out2[mt][2*kt+1][1]);
            }
            float slo = 0.f, shi = 0.f;
#pragma unroll
            for (int nt = 0; nt < 4; nt++) {
                float c0 = CB1c0[nt], c1 = CB1c1[nt], c2 = CB1c0[nt], c3 = CB1c1[nt];
                mma16816(c0, c1, c2, c3, A0[0][0], A0[0][1], A0[0][2], A0[0][3],
                         CB[0][nt][0], CB[0][nt][1]);
                mma16816(c0, c1, c2, c3, A0[1][0], A0[1][1], A0[1][2], A0[1][3],
                         CB[1][nt][0], CB[1][nt][1]);
                bf2 p0 = silu_b(u2b(packf(c0, c1)));
                bf2 p1 = silu_b(u2b(packf(c2, c3)));
                float2 q0 = __bfloat1622float2(__hmul2(p0, u2b(CW2p[nt])));
                float2 q1 = __bfloat1622float2(__hmul2(p1, u2b(CW2p[nt])));
                slo += q0.x + q0.y;
                shi += q1.x + q1.y;
            }
            pl[2*mt]     = slo;
            pl[2*mt + 1] = shi;
        }
        // reduce over t within each group of 4 lanes
#pragma unroll
        for (int d = 1; d <= 2; d <<= 1) {
            pl[0] += __shfl_xor_sync(0xffffffffu, pl[0], d);
            pl[1] += __shfl_xor_sync(0xffffffffu, pl[1], d);
            pl[2] += __shfl_xor_sync(0xffffffffu, pl[2], d);
            pl[3] += __shfl_xor_sync(0xffffffffu, pl[3], d);
        }
        // fetch this lane's own edge cm: edge = lane = mt*16 + hi*8 + g'
        int src = 4 * (lane & 7);
        float r0 = __shfl_sync(0xffffffffu, pl[0], src);
        float r1 = __shfl_sync(0xffffffffu, pl[1], src);
        float r2 = __shfl_sync(0xffffffffu, pl[2], src);
        float r3 = __shfl_sync(0xffffffffu, pl[3], src);
        int sel = lane >> 3;
        float cm = (sel == 0) ? r0 : (sel == 1) ? r1 : (sel == 2) ? r2 : r3;

        // ---- scatters -------------------------------------------------------
#pragma unroll
        for (int mt = 0; mt < 2; mt++) {
            int eA = base + mt*16 + g;
            int eB = eA + 8;
            bool vA = (eA < E), vB = (eB < E);
            int rA = mR[mt*16 + g];
            int rB = mR[mt*16 + g + 8];
#pragma unroll
            for (int nt = 0; nt < 4; nt++) {
                int j0 = 8*nt + 2*t;
                float2 fA = __bfloat1622float2(out2[mt][nt][0]);
                float2 fB = __bfloat1622float2(out2[mt][nt][1]);
                if (vA) red_add_v2(&g_magg[rA*H + j0], fA.x, fA.y);
                if (vB) red_add_v2(&g_magg[rB*H + j0], fB.x, fB.y);
            }
        }
        if (vme) {
            float* tago = &g_tagg[row * DX];
#pragma unroll
            for (int q = 0; q < 4; q++) {
                float2 d0 = __bfloat1622float2(cd[2*q]);
                float2 d1 = __bfloat1622float2(cd[2*q+1]);
                red_add_v4(tago + 4*q, d0.x*cm, d0.y*cm, d1.x*cm, d1.y*cm);
            }
        }
        __syncwarp();
    }
}

// ---------------------------------------------------------------------------
#define NTPB 128

__global__ __launch_bounds__(NTPB, 4) void node_kernel(
    const float* __restrict__ nW1, const float* __restrict__ nb1,
    const float* __restrict__ nW2, const float* __restrict__ nb2,
    const float* __restrict__ eW1n, const float* __restrict__ eb1n,
    const float* __restrict__ linW, float* __restrict__ out, int n)
{
    __shared__ __align__(16) float sN1t[2 * H][H];
    __shared__ __align__(16) float sN2t[H][H];
    __shared__ __align__(16) float sEAt[H][H];
    __shared__ __align__(16) float sEBt[H][H];

    int i = blockIdx.x * NTPB + threadIdx.x;
    bool active = (i < n);

    float cnt = 0.f;
    float4 xr[4], tr[4], hr[8], mr[8];
    if (active) {
        cnt = g_cnt[i];
        const float4* xp = (const float4*)&g_x[i * DX];
        const float4* tp = (const float4*)&g_tagg[i * DX];
        const float4* hp = (const float4*)&g_h[i * H];
        const float4* mp = (const float4*)&g_magg[i * H];
#pragma unroll
        for (int q = 0; q < 4; q++) { xr[q] = xp[q]; tr[q] = tp[q]; }
#pragma unroll
        for (int q = 0; q < 8; q++) { hr[q] = hp[q]; mr[q] = mp[q]; }
    }

    for (int idx = threadIdx.x; idx < H * 2 * H; idx += NTPB) {
        int j = idx >> 6, k = idx & 63;
        sN1t[k][j] = nW1[idx];
    }
    for (int idx = threadIdx.x; idx < H * H; idx += NTPB) {
        int j = idx >> 5, k = idx & 31;
        sN2t[k][j] = nW2[idx];
        if (eW1n) {
            sEAt[k][j] = eW1n[j * 68 + k];
            sEBt[k][j] = eW1n[j * 68 + 32 + k];
        }
    }
    __syncthreads();

    if (!active) return;

    float inv = 1.0f / fmaxf(cnt, 1.0f);
    const float4 z4 = make_float4(0.f, 0.f, 0.f, 0.f);

    float xv[DX];
    float4* xp = (float4*)&g_x[i * DX];
    float4* tp = (float4*)&g_tagg[i * DX];
#pragma unroll
    for (int q = 0; q < 4; q++) {
        xv[4*q]   = xr[q].x + tr[q].x * inv;
        xv[4*q+1] = xr[q].y + tr[q].y * inv;
        xv[4*q+2] = xr[q].z + tr[q].z * inv;
        xv[4*q+3] = xr[q].w + tr[q].w * inv;
        xp[q] = make_float4(xv[4*q], xv[4*q+1], xv[4*q+2], xv[4*q+3]);
        tp[q] = z4;
    }

    float hv[H], mg[H];
    float4* mp = (float4*)&g_magg[i * H];
#pragma unroll
    for (int q = 0; q < 8; q++) {
        hv[4*q] = hr[q].x; hv[4*q+1] = hr[q].y; hv[4*q+2] = hr[q].z; hv[4*q+3] = hr[q].w;
        mg[4*q] = mr[q].x; mg[4*q+1] = mr[q].y; mg[4*q+2] = mr[q].z; mg[4*q+3] = mr[q].w;
        mp[q] = z4;
    }

    float u[H];
#pragma unroll
    for (int j = 0; j < H; j++) u[j] = nb1[j];
#pragma unroll
    for (int k = 0; k < H; k++) {
        float v = hv[k];
        const float4* w4 = (const float4*)&sN1t[k][0];
#pragma unroll
        for (int q = 0; q < 8; q++) {
            float4 w = w4[q];
            u[4*q] += w.x*v; u[4*q+1] += w.y*v; u[4*q+2] += w.z*v; u[4*q+3] += w.w*v;
        }
    }
#pragma unroll
    for (int k = 0; k < H; k++) {
        float v = mg[k];
        const float4* w4 = (const float4*)&sN1t[H + k][0];
#pragma unroll
        for (int q = 0; q < 8; q++) {
            float4 w = w4[q];
            u[4*q] += w.x*v; u[4*q+1] += w.y*v; u[4*q+2] += w.z*v; u[4*q+3] += w.w*v;
        }
    }
#pragma unroll
    for (int j = 0; j < H; j++) u[j] = silu_f(u[j]);

    float hn[H];
#pragma unroll
    for (int j = 0; j < H; j++) hn[j] = nb2[j];
#pragma unroll
    for (int k = 0; k < H; k++) {
        float v = u[k];
        const float4* w4 = (const float4*)&sN2t[k][0];
#pragma unroll
        for (int q = 0; q < 8; q++) {
            float4 w = w4[q];
            hn[4*q] += w.x*v; hn[4*q+1] += w.y*v; hn[4*q+2] += w.z*v; hn[4*q+3] += w.w*v;
        }
    }
#pragma unroll
    for (int j = 0; j < H; j++) hn[j] += hv[j];
    float4* hp = (float4*)&g_h[i * H];
#pragma unroll
    for (int q = 0; q < 8; q++)
        hp[q] = make_float4(hn[4*q], hn[4*q+1], hn[4*q+2], hn[4*q+3]);

    if (eW1n) {
        float Av[H], Bv[H];
#pragma unroll
        for (int j = 0; j < H; j++) { Av[j] = eb1n[j]; Bv[j] = 0.0f; }
#pragma unroll
        for (int k = 0; k < H; k++) {
            float v = hn[k];
            const float4* wa = (const float4*)&sEAt[k][0];
            const float4* wb = (const float4*)&sEBt[k][0];
#pragma unroll
            for (int q = 0; q < 8; q++) {
                float4 a = wa[q], b = wb[q];
                Av[4*q] += a.x*v; Av[4*q+1] += a.y*v; Av[4*q+2] += a.z*v; Av[4*q+3] += a.w*v;
                Bv[4*q] += b.x*v; Bv[4*q+1] += b.y*v; Bv[4*q+2] += b.z*v; Bv[4*q+3] += b.w*v;
            }
        }
        u32 pa[HQ], pb[HQ];
#pragma unroll
        for (int jq = 0; jq < HQ; jq++) {
            pa[jq] = packf(Av[2*jq], Av[2*jq+1]);
            pb[jq] = packf(Bv[2*jq], Bv[2*jq+1]);
        }
        uint4* Ao = (uint4*)&g_A[i * HQ];
        uint4* Bo = (uint4*)&g_B[i * HQ];
#pragma unroll
        for (int q = 0; q < 4; q++) {
            Ao[q] = make_uint4(pa[4*q], pa[4*q+1], pa[4*q+2], pa[4*q+3]);
            Bo[q] = make_uint4(pb[4*q], pb[4*q+1], pb[4*q+2], pb[4*q+3]);
        }
    }

    if (linW) {
#pragma unroll
        for (int c = 0; c < 3; c++) {
            float acc = 0.0f;
#pragma unroll
            for (int k = 0; k < DX; k++) acc += linW[c * DX + k] * xv[k];
            out[i * 3 + c] = acc;
        }
    }
}

extern "C" void kernel_launch(void* const* d_in, const int* in_sizes, int n_in,
                              void* d_out, int out_size)
{
    const float* node_attrs = (const float*)d_in[0];
    const float* positions  = (const float*)d_in[1];
    const int*   edge_index = (const int*)  d_in[2];
    const float* proj_W     = (const float*)d_in[3];
    const float* emb_in_W   = (const float*)d_in[4];
    const float* emb_in_b   = (const float*)d_in[5];
    const float* edge_W1    = (const float*)d_in[6];
    const float* edge_b1    = (const float*)d_in[7];
    const float* edge_W2    = (const float*)d_in[8];
    const float* edge_b2    = (const float*)d_in[9];
    const float* node_W1    = (const float*)d_in[10];
    const float* node_b1    = (const float*)d_in[11];
    const float* node_W2    = (const float*)d_in[12];
    const float* node_b2    = (const float*)d_in[13];
    const float* coord_W1   = (const float*)d_in[14];
    const float* coord_b1   = (const float*)d_in[15];
    const float* coord_W2   = (const float*)d_in[16];
    const float* lin_W      = (const float*)d_in[19];

    int n = in_sizes[0] / 3;
    int E = in_sizes[2] / 2;
    float* out = (float*)d_out;

    init_kernel<<<(n + 127) / 128, 128>>>(node_attrs, positions, proj_W,
                                          emb_in_W, emb_in_b, edge_W1, edge_b1, n);
    count_kernel<<<(E + 255) / 256, 256>>>(edge_index, E);
    nop_kernel<<<1, 32>>>();

    int eblocks = 444;  // grid-stride; 3 blocks/SM on 148 SMs
    int nblocks = (n + NTPB - 1) / NTPB;

    for (int l = 0; l < 2; l++) {
        edge_kernel<<<eblocks, EBLK>>>(
            edge_index, E, positions,
            edge_W1 + l * H * 68,
            edge_W2 + l * H * H, edge_b2 + l * H,
            coord_W1 + l * H * H, coord_b1 + l * H,
            coord_W2 + l * H);
        node_kernel<<<nblocks, NTPB>>>(
            node_W1 + l * H * 2 * H, node_b1 + l * H,
            node_W2 + l * H * H,     node_b2 + l * H,
            (l == 0) ? edge_W1 + H * 68 : nullptr,
            (l == 0) ? edge_b1 + H      : nullptr,
            (l == 1) ? lin_W            : nullptr,
            out, n);
    }
}

// round 16
// speedup vs baseline: 1.7698x; 1.1124x over previous
#include <cuda_runtime.h>
#include <cuda_bf16.h>

#define H    32
#define DX   16
#define HQ   16
#define NMAX 50048

typedef unsigned long long u64;
typedef unsigned int u32;
typedef __nv_bfloat162 bf2;

__device__ __align__(16) float g_x[NMAX * DX];
__device__ __align__(16) u32 g_xb[NMAX * 8];     // bf16 mirror of x (16 vals)
__device__ __align__(16) float4 g_pos4[NMAX];    // padded positions
__device__ __align__(16) float g_h[NMAX * H];
__device__ __align__(16) u32 g_A[NMAX * HQ];
__device__ __align__(16) u32 g_B[NMAX * HQ];
__device__ __align__(16) float g_magg[NMAX * H];
__device__ __align__(16) float g_tagg[NMAX * DX];
__device__ float g_cnt[NMAX];
__device__ int g_dummy;

__device__ __forceinline__ float silu_f(float v) {
    return v * (1.0f / (1.0f + __expf(-v)));
}
__device__ __forceinline__ u32 b2u(bf2 v) { return *reinterpret_cast<u32*>(&v); }
__device__ __forceinline__ bf2 u2b(u32 v) { return *reinterpret_cast<bf2*>(&v); }

__device__ __forceinline__ bf2 silu_b(bf2 v) {
    bf2 h = __hmul2(v, __float2bfloat162_rn(0.5f));
    u32 tu;
    u32 hu = b2u(h);
    asm("tanh.approx.bf16x2 %0, %1;" : "=r"(tu) : "r"(hu));
    return __hmul2(h, __hadd2(u2b(tu), __float2bfloat162_rn(1.0f)));
}

// pack two f32 into bf16x2 (lo first)
__device__ __forceinline__ u32 packf(float lo, float hi) {
    u32 r; asm("cvt.rn.bf16x2.f32 %0, %1, %2;" : "=r"(r) : "f"(hi), "f"(lo)); return r;
}

__device__ __forceinline__ void mma16816(float& c0, float& c1, float& c2, float& c3,
                                         u32 a0, u32 a1, u32 a2, u32 a3, u32 b0, u32 b1) {
    asm("mma.sync.aligned.m16n8k16.row.col.f32.bf16.bf16.f32 "
        "{%0,%1,%2,%3},{%4,%5,%6,%7},{%8,%9},{%0,%1,%2,%3};"
        : "+f"(c0), "+f"(c1), "+f"(c2), "+f"(c3)
        : "r"(a0), "r"(a1), "r"(a2), "r"(a3), "r"(b0), "r"(b1));
}

__device__ __forceinline__ void red_add_v4(float* a, float x, float y, float z, float w) {
    asm volatile("red.global.add.v4.f32 [%0], {%1,%2,%3,%4};"
                 :: "l"(a), "f"(x), "f"(y), "f"(z), "f"(w) : "memory");
}
__device__ __forceinline__ void red_add_v2(float* a, float x, float y) {
    asm volatile("red.global.add.v2.f32 [%0], {%1,%2};"
                 :: "l"(a), "f"(x), "f"(y) : "memory");
}

// ---------------------------------------------------------------------------
__global__ __launch_bounds__(128, 4) void init_kernel(
    const float* __restrict__ attrs, const float* __restrict__ pos,
    const float* __restrict__ projW, const float* __restrict__ embW,
    const float* __restrict__ embB, const float* __restrict__ eW1,
    const float* __restrict__ eb1, int n)
{
    __shared__ __align__(16) float sWa[H][H];
    __shared__ __align__(16) float sWb[H][H];
    for (int idx = threadIdx.x; idx < H * H; idx += 128) {
        int j = idx >> 5, k = idx & 31;
        sWa[k][j] = eW1[j * 68 + k];
        sWb[k][j] = eW1[j * 68 + 32 + k];
    }
    __syncthreads();
    int i = blockIdx.x * 128 + threadIdx.x;
    if (i >= n) return;

    float p0 = pos[i*3], p1 = pos[i*3+1], p2 = pos[i*3+2];
    g_pos4[i] = make_float4(p0, p1, p2, 0.0f);

    float xv[DX];
#pragma unroll
    for (int j = 0; j < DX; j++)
        xv[j] = projW[j*3]*p0 + projW[j*3+1]*p1 + projW[j*3+2]*p2;
    float4* xo = (float4*)&g_x[i * DX];
#pragma unroll
    for (int q = 0; q < 4; q++)
        xo[q] = make_float4(xv[4*q], xv[4*q+1], xv[4*q+2], xv[4*q+3]);
    uint4* xb = (uint4*)&g_xb[i * 8];
#pragma unroll
    for (int q = 0; q < 2; q++)
        xb[q] = make_uint4(packf(xv[8*q],   xv[8*q+1]), packf(xv[8*q+2], xv[8*q+3]),
                           packf(xv[8*q+4], xv[8*q+5]), packf(xv[8*q+6], xv[8*q+7]));

    float a0 = attrs[i*3], a1 = attrs[i*3+1], a2 = attrs[i*3+2];
    float hv[H];
#pragma unroll
    for (int j = 0; j < H; j++)
        hv[j] = embW[j*3]*a0 + embW[j*3+1]*a1 + embW[j*3+2]*a2 + embB[j];
    float4* ho = (float4*)&g_h[i * H];
#pragma unroll
    for (int q = 0; q < 8; q++)
        ho[q] = make_float4(hv[4*q], hv[4*q+1], hv[4*q+2], hv[4*q+3]);

    float Av[H], Bv[H];
#pragma unroll
    for (int j = 0; j < H; j++) { Av[j] = eb1[j]; Bv[j] = 0.0f; }
#pragma unroll
    for (int k = 0; k < H; k++) {
        float hk = hv[k];
        const float4* wa = (const float4*)&sWa[k][0];
        const float4* wb = (const float4*)&sWb[k][0];
#pragma unroll
        for (int q = 0; q < 8; q++) {
            float4 a = wa[q], b = wb[q];
            Av[4*q] += a.x*hk; Av[4*q+1] += a.y*hk; Av[4*q+2] += a.z*hk; Av[4*q+3] += a.w*hk;
            Bv[4*q] += b.x*hk; Bv[4*q+1] += b.y*hk; Bv[4*q+2] += b.z*hk; Bv[4*q+3] += b.w*hk;
        }
    }
    u32 pa[HQ], pb[HQ];
#pragma unroll
    for (int jq = 0; jq < HQ; jq++) {
        pa[jq] = packf(Av[2*jq], Av[2*jq+1]);
        pb[jq] = packf(Bv[2*jq], Bv[2*jq+1]);
    }
    uint4* Ao = (uint4*)&g_A[i * HQ];
    uint4* Bo = (uint4*)&g_B[i * HQ];
#pragma unroll
    for (int q = 0; q < 4; q++) {
        Ao[q] = make_uint4(pa[4*q], pa[4*q+1], pa[4*q+2], pa[4*q+3]);
        Bo[q] = make_uint4(pb[4*q], pb[4*q+1], pb[4*q+2], pb[4*q+3]);
    }

    const float4 z4 = make_float4(0.f, 0.f, 0.f, 0.f);
    float4* mz = (float4*)&g_magg[i * H];
    float4* tz = (float4*)&g_tagg[i * DX];
#pragma unroll
    for (int q = 0; q < 8; q++) mz[q] = z4;
#pragma unroll
    for (int q = 0; q < 4; q++) tz[q] = z4;
    g_cnt[i] = 0.0f;
}

__global__ void count_kernel(const int* __restrict__ ei, int E)
{
    int e = blockIdx.x * blockDim.x + threadIdx.x;
    if (e < E) atomicAdd(&g_cnt[ei[e]], 1.0f);
}

__global__ void nop_kernel() { if (blockIdx.x == 1u << 30) g_dummy = 1; }

// ---------------------------------------------------------------------------
// edge kernel: warp = 32 edges; mma.sync bf16 with register weights,
// gathers via g_pos4 (1 LDG.128/node) and g_xb (2 LDG.128/node).
// ---------------------------------------------------------------------------
#define EBLK 128
#define SSTR 80

__global__ __launch_bounds__(EBLK) void edge_kernel(
    const int* __restrict__ ei, int E,
    const float* __restrict__ W1,   // [32][68], cols 64..67 = geo coeffs
    const float* __restrict__ W2,   // [32][32]
    const float* __restrict__ b2,
    const float* __restrict__ cW1,  // [32][32]
    const float* __restrict__ cb1,
    const float* __restrict__ cW2)  // [32]
{
    __shared__ __align__(16) unsigned char sS[4][32 * SSTR];
    __shared__ __align__(8)  u32 sG[4][32 * 2];
    __shared__ int sRow[4][32];

    int tid = threadIdx.x, wid = tid >> 5, lane = tid & 31;
    int g = lane >> 2, t = lane & 3;

    // one-time register weight fragments
    u32 WB[2][4][2], CB[2][4][2], GB[4];
    float B2c0[4], B2c1[4], CB1c0[4], CB1c1[4];
    u32 CW2p[4];
#pragma unroll
    for (int nt = 0; nt < 4; nt++) {
        int j = 8 * nt + g;
#pragma unroll
        for (int kt = 0; kt < 2; kt++) {
            int k0 = 16 * kt + 2 * t;
            WB[kt][nt][0] = packf(W2[j*H + k0],     W2[j*H + k0 + 1]);
            WB[kt][nt][1] = packf(W2[j*H + k0 + 8], W2[j*H + k0 + 9]);
            CB[kt][nt][0] = packf(cW1[j*H + k0],     cW1[j*H + k0 + 1]);
            CB[kt][nt][1] = packf(cW1[j*H + k0 + 8], cW1[j*H + k0 + 9]);
        }
        float glo = 0.f, ghi = 0.f;
        if (t == 0) { glo = W1[j*68 + 64]; ghi = W1[j*68 + 65]; }
        else if (t == 1) { glo = W1[j*68 + 66]; ghi = W1[j*68 + 67]; }
        GB[nt] = packf(glo, ghi);

        int jc = 8 * nt + 2 * t;
        B2c0[nt]  = b2[jc];   B2c1[nt]  = b2[jc + 1];
        CB1c0[nt] = cb1[jc];  CB1c1[nt] = cb1[jc + 1];
        CW2p[nt]  = packf(cW2[jc], cW2[jc + 1]);
    }

    unsigned char* mS = &sS[wid][0];
    u32* mG = &sG[wid][0];
    int* mR = &sRow[wid][0];

    int warps_total = gridDim.x * (EBLK / 32);
    int wgl = blockIdx.x * (EBLK / 32) + wid;

    for (int base = wgl * 32; base < E; base += warps_total * 32) {
        int e = base + lane;
        bool vme = (e < E);
        int ec = vme ? e : (E - 1);
        int row = ei[ec], col = ei[E + ec];
        mR[lane] = row;

        float4 pr = g_pos4[row];
        float4 pc = g_pos4[col];
        float ea0 = pr.x - pc.x;
        float ea1 = pr.y - pc.y;
        float ea2 = pr.z - pc.z;

        bf2 cd[8];
        float radial = 0.0f;
        {
            const uint4* xr = (const uint4*)&g_xb[row * 8];
            const uint4* xc = (const uint4*)&g_xb[col * 8];
#pragma unroll
            for (int q = 0; q < 2; q++) {
                uint4 a4 = xr[q], b4 = xc[q];
                const u32* ap = (const u32*)&a4;
                const u32* bp = (const u32*)&b4;
#pragma unroll
                for (int r = 0; r < 4; r++) {
                    float2 af = __bfloat1622float2(u2b(ap[r]));
                    float2 bf = __bfloat1622float2(u2b(bp[r]));
                    float d0 = af.x - bf.x, d1 = af.y - bf.y;
                    cd[4*q + r] = u2b(packf(d0, d1));
                    radial += d0*d0 + d1*d1;
                }
            }
        }

        // stage geo and A[row]+B[col] sums
        mG[lane*2 + 0] = packf(radial, ea0);
        mG[lane*2 + 1] = packf(ea1, ea2);
        {
            const uint4* Ar = (const uint4*)&g_A[row * HQ];
            const uint4* Bc = (const uint4*)&g_B[col * HQ];
            uint4* dst = (uint4*)&mS[lane * SSTR];
#pragma unroll
            for (int q = 0; q < 4; q++) {
                uint4 a4 = Ar[q], b4 = Bc[q];
                uint4 o;
                o.x = b2u(__hadd2(u2b(a4.x), u2b(b4.x)));
                o.y = b2u(__hadd2(u2b(a4.y), u2b(b4.y)));
                o.z = b2u(__hadd2(u2b(a4.z), u2b(b4.z)));
                o.w = b2u(__hadd2(u2b(a4.w), u2b(b4.w)));
                dst[q] = o;
            }
        }
        __syncwarp();

        // layer 1
        bf2 msm[2][4][2];
#pragma unroll
        for (int mt = 0; mt < 2; mt++) {
            u32 ga0 = 0, ga1 = 0;
            if (t < 2) {
                ga0 = mG[(mt*16 + g) * 2 + t];
                ga1 = mG[(mt*16 + g + 8) * 2 + t];
            }
#pragma unroll
            for (int nt = 0; nt < 4; nt++) {
                u32 s0 = *(const u32*)&mS[(mt*16 + g) * SSTR + 16*nt + 4*t];
                u32 s1 = *(const u32*)&mS[(mt*16 + g + 8) * SSTR + 16*nt + 4*t];
                float2 f0 = __bfloat1622float2(u2b(s0));
                float2 f1 = __bfloat1622float2(u2b(s1));
                float c0 = f0.x, c1 = f0.y, c2 = f1.x, c3 = f1.y;
                mma16816(c0, c1, c2, c3, ga0, ga1, 0u, 0u, GB[nt], 0u);
                msm[mt][nt][0] = silu_b(u2b(packf(c0, c1)));
                msm[mt][nt][1] = silu_b(u2b(packf(c2, c3)));
            }
        }

        // layer 2
        bf2 out2[2][4][2];
#pragma unroll
        for (int mt = 0; mt < 2; mt++) {
            u32 A0[2][4];
#pragma unroll
            for (int kt = 0; kt < 2; kt++) {
                A0[kt][0] = b2u(msm[mt][2*kt][0]);
                A0[kt][1] = b2u(msm[mt][2*kt][1]);
                A0[kt][2] = b2u(msm[mt][2*kt+1][0]);
                A0[kt][3] = b2u(msm[mt][2*kt+1][1]);
            }
#pragma unroll
            for (int nt = 0; nt < 4; nt++) {
                float c0 = B2c0[nt], c1 = B2c1[nt], c2 = B2c0[nt], c3 = B2c1[nt];
                mma16816(c0, c1, c2, c3, A0[0][0], A0[0][1], A0[0][2], A0[0][3],
                         WB[0][nt][0], WB[0][nt][1]);
                mma16816(c0, c1, c2, c3, A0[1][0], A0[1][1], A0[1][2], A0[1][3],
                         WB[1][nt][0], WB[1][nt][1]);
                out2[mt][nt][0] = silu_b(u2b(packf(c0, c1)));
                out2[mt][nt][1] = silu_b(u2b(packf(c2, c3)));
            }
        }

        // coord head
        float pl[4];
#pragma unroll
        for (int mt = 0; mt < 2; mt++) {
            u32 A0[2][4];
#pragma unroll
            for (int kt = 0; kt < 2; kt++) {
                A0[kt][0] = b2u(out2[mt][2*kt][0]);
                A0[kt][1] = b2u(out2[mt][2*kt][1]);
                A0[kt][2] = b2u(out2[mt][2*kt+1][0]);
                A0[kt][3] = b2u(out2[mt][2*kt+1][1]);
            }
            float slo = 0.f, shi = 0.f;
#pragma unroll
            for (int nt = 0; nt < 4; nt++) {
                float c0 = CB1c0[nt], c1 = CB1c1[nt], c2 = CB1c0[nt], c3 = CB1c1[nt];
                mma16816(c0, c1, c2, c3, A0[0][0], A0[0][1], A0[0][2], A0[0][3],
                         CB[0][nt][0], CB[0][nt][1]);
                mma16816(c0, c1, c2, c3, A0[1][0], A0[1][1], A0[1][2], A0[1][3],
                         CB[1][nt][0], CB[1][nt][1]);
                bf2 p0 = silu_b(u2b(packf(c0, c1)));
                bf2 p1 = silu_b(u2b(packf(c2, c3)));
                float2 q0 = __bfloat1622float2(__hmul2(p0, u2b(CW2p[nt])));
                float2 q1 = __bfloat1622float2(__hmul2(p1, u2b(CW2p[nt])));
                slo += q0.x + q0.y;
                shi += q1.x + q1.y;
            }
            pl[2*mt]     = slo;
            pl[2*mt + 1] = shi;
        }
#pragma unroll
        for (int d = 1; d <= 2; d <<= 1) {
            pl[0] += __shfl_xor_sync(0xffffffffu, pl[0], d);
            pl[1] += __shfl_xor_sync(0xffffffffu, pl[1], d);
            pl[2] += __shfl_xor_sync(0xffffffffu, pl[2], d);
            pl[3] += __shfl_xor_sync(0xffffffffu, pl[3], d);
        }
        int src = 4 * (lane & 7);
        float r0 = __shfl_sync(0xffffffffu, pl[0], src);
        float r1 = __shfl_sync(0xffffffffu, pl[1], src);
        float r2 = __shfl_sync(0xffffffffu, pl[2], src);
        float r3 = __shfl_sync(0xffffffffu, pl[3], src);
        int sel = lane >> 3;
        float cm = (sel == 0) ? r0 : (sel == 1) ? r1 : (sel == 2) ? r2 : r3;

        // scatters
#pragma unroll
        for (int mt = 0; mt < 2; mt++) {
            int eA = base + mt*16 + g;
            int eB = eA + 8;
            bool vA = (eA < E), vB = (eB < E);
            int rA = mR[mt*16 + g];
            int rB = mR[mt*16 + g + 8];
#pragma unroll
            for (int nt = 0; nt < 4; nt++) {
                int j0 = 8*nt + 2*t;
                float2 fA = __bfloat1622float2(out2[mt][nt][0]);
                float2 fB = __bfloat1622float2(out2[mt][nt][1]);
                if (vA) red_add_v2(&g_magg[rA*H + j0], fA.x, fA.y);
                if (vB) red_add_v2(&g_magg[rB*H + j0], fB.x, fB.y);
            }
        }
        if (vme) {
            float* tago = &g_tagg[row * DX];
#pragma unroll
            for (int q = 0; q < 4; q++) {
                float2 d0 = __bfloat1622float2(cd[2*q]);
                float2 d1 = __bfloat1622float2(cd[2*q+1]);
                red_add_v4(tago + 4*q, d0.x*cm, d0.y*cm, d1.x*cm, d1.y*cm);
            }
        }
        __syncwarp();
    }
}

// ---------------------------------------------------------------------------
#define NTPB 128

__global__ __launch_bounds__(NTPB, 4) void node_kernel(
    const float* __restrict__ nW1, const float* __restrict__ nb1,
    const float* __restrict__ nW2, const float* __restrict__ nb2,
    const float* __restrict__ eW1n, const float* __restrict__ eb1n,
    const float* __restrict__ linW, float* __restrict__ out, int n)
{
    __shared__ __align__(16) float sN1t[2 * H][H];
    __shared__ __align__(16) float sN2t[H][H];
    __shared__ __align__(16) float sEAt[H][H];
    __shared__ __align__(16) float sEBt[H][H];

    int i = blockIdx.x * NTPB + threadIdx.x;
    bool active = (i < n);

    float cnt = 0.f;
    float4 xr[4], tr[4], hr[8], mr[8];
    if (active) {
        cnt = g_cnt[i];
        const float4* xp = (const float4*)&g_x[i * DX];
        const float4* tp = (const float4*)&g_tagg[i * DX];
        const float4* hp = (const float4*)&g_h[i * H];
        const float4* mp = (const float4*)&g_magg[i * H];
#pragma unroll
        for (int q = 0; q < 4; q++) { xr[q] = xp[q]; tr[q] = tp[q]; }
#pragma unroll
        for (int q = 0; q < 8; q++) { hr[q] = hp[q]; mr[q] = mp[q]; }
    }

    for (int idx = threadIdx.x; idx < H * 2 * H; idx += NTPB) {
        int j = idx >> 6, k = idx & 63;
        sN1t[k][j] = nW1[idx];
    }
    for (int idx = threadIdx.x; idx < H * H; idx += NTPB) {
        int j = idx >> 5, k = idx & 31;
        sN2t[k][j] = nW2[idx];
        if (eW1n) {
            sEAt[k][j] = eW1n[j * 68 + k];
            sEBt[k][j] = eW1n[j * 68 + 32 + k];
        }
    }
    __syncthreads();

    if (!active) return;

    float inv = 1.0f / fmaxf(cnt, 1.0f);
    const float4 z4 = make_float4(0.f, 0.f, 0.f, 0.f);

    float xv[DX];
    float4* xp = (float4*)&g_x[i * DX];
    float4* tp = (float4*)&g_tagg[i * DX];
#pragma unroll
    for (int q = 0; q < 4; q++) {
        xv[4*q]   = xr[q].x + tr[q].x * inv;
        xv[4*q+1] = xr[q].y + tr[q].y * inv;
        xv[4*q+2] = xr[q].z + tr[q].z * inv;
        xv[4*q+3] = xr[q].w + tr[q].w * inv;
        xp[q] = make_float4(xv[4*q], xv[4*q+1], xv[4*q+2], xv[4*q+3]);
        tp[q] = z4;
    }
    uint4* xb = (uint4*)&g_xb[i * 8];
#pragma unroll
    for (int q = 0; q < 2; q++)
        xb[q] = make_uint4(packf(xv[8*q],   xv[8*q+1]), packf(xv[8*q+2], xv[8*q+3]),
                           packf(xv[8*q+4], xv[8*q+5]), packf(xv[8*q+6], xv[8*q+7]));

    float hv[H], mg[H];
    float4* mp = (float4*)&g_magg[i * H];
#pragma unroll
    for (int q = 0; q < 8; q++) {
        hv[4*q] = hr[q].x; hv[4*q+1] = hr[q].y; hv[4*q+2] = hr[q].z; hv[4*q+3] = hr[q].w;
        mg[4*q] = mr[q].x; mg[4*q+1] = mr[q].y; mg[4*q+2] = mr[q].z; mg[4*q+3] = mr[q].w;
        mp[q] = z4;
    }

    float u[H];
#pragma unroll
    for (int j = 0; j < H; j++) u[j] = nb1[j];
#pragma unroll
    for (int k = 0; k < H; k++) {
        float v = hv[k];
        const float4* w4 = (const float4*)&sN1t[k][0];
#pragma unroll
        for (int q = 0; q < 8; q++) {
            float4 w = w4[q];
            u[4*q] += w.x*v; u[4*q+1] += w.y*v; u[4*q+2] += w.z*v; u[4*q+3] += w.w*v;
        }
    }
#pragma unroll
    for (int k = 0; k < H; k++) {
        float v = mg[k];
        const float4* w4 = (const float4*)&sN1t[H + k][0];
#pragma unroll
        for (int q = 0; q < 8; q++) {
            float4 w = w4[q];
            u[4*q] += w.x*v; u[4*q+1] += w.y*v; u[4*q+2] += w.z*v; u[4*q+3] += w.w*v;
        }
    }
#pragma unroll
    for (int j = 0; j < H; j++) u[j] = silu_f(u[j]);

    float hn[H];
#pragma unroll
    for (int j = 0; j < H; j++) hn[j] = nb2[j];
#pragma unroll
    for (int k = 0; k < H; k++) {
        float v = u[k];
        const float4* w4 = (const float4*)&sN2t[k][0];
#pragma unroll
        for (int q = 0; q < 8; q++) {
            float4 w = w4[q];
            hn[4*q] += w.x*v; hn[4*q+1] += w.y*v; hn[4*q+2] += w.z*v; hn[4*q+3] += w.w*v;
        }
    }
#pragma unroll
    for (int j = 0; j < H; j++) hn[j] += hv[j];
    float4* hp = (float4*)&g_h[i * H];
#pragma unroll
    for (int q = 0; q < 8; q++)
        hp[q] = make_float4(hn[4*q], hn[4*q+1], hn[4*q+2], hn[4*q+3]);

    if (eW1n) {
        float Av[H], Bv[H];
#pragma unroll
        for (int j = 0; j < H; j++) { Av[j] = eb1n[j]; Bv[j] = 0.0f; }
#pragma unroll
        for (int k = 0; k < H; k++) {
            float v = hn[k];
            const float4* wa = (const float4*)&sEAt[k][0];
            const float4* wb = (const float4*)&sEBt[k][0];
#pragma unroll
            for (int q = 0; q < 8; q++) {
                float4 a = wa[q], b = wb[q];
                Av[4*q] += a.x*v; Av[4*q+1] += a.y*v; Av[4*q+2] += a.z*v; Av[4*q+3] += a.w*v;
                Bv[4*q] += b.x*v; Bv[4*q+1] += b.y*v; Bv[4*q+2] += b.z*v; Bv[4*q+3] += b.w*v;
            }
        }
        u32 pa[HQ], pb[HQ];
#pragma unroll
        for (int jq = 0; jq < HQ; jq++) {
            pa[jq] = packf(Av[2*jq], Av[2*jq+1]);
            pb[jq] = packf(Bv[2*jq], Bv[2*jq+1]);
        }
        uint4* Ao = (uint4*)&g_A[i * HQ];
        uint4* Bo = (uint4*)&g_B[i * HQ];
#pragma unroll
        for (int q = 0; q < 4; q++) {
            Ao[q] = make_uint4(pa[4*q], pa[4*q+1], pa[4*q+2], pa[4*q+3]);
            Bo[q] = make_uint4(pb[4*q], pb[4*q+1], pb[4*q+2], pb[4*q+3]);
        }
    }

    if (linW) {
#pragma unroll
        for (int c = 0; c < 3; c++) {
            float acc = 0.0f;
#pragma unroll
            for (int k = 0; k < DX; k++) acc += linW[c * DX + k] * xv[k];
            out[i * 3 + c] = acc;
        }
    }
}

extern "C" void kernel_launch(void* const* d_in, const int* in_sizes, int n_in,
                              void* d_out, int out_size)
{
    const float* node_attrs = (const float*)d_in[0];
    const float* positions  = (const float*)d_in[1];
    const int*   edge_index = (const int*)  d_in[2];
    const float* proj_W     = (const float*)d_in[3];
    const float* emb_in_W   = (const float*)d_in[4];
    const float* emb_in_b   = (const float*)d_in[5];
    const float* edge_W1    = (const float*)d_in[6];
    const float* edge_b1    = (const float*)d_in[7];
    const float* edge_W2    = (const float*)d_in[8];
    const float* edge_b2    = (const float*)d_in[9];
    const float* node_W1    = (const float*)d_in[10];
    const float* node_b1    = (const float*)d_in[11];
    const float* node_W2    = (const float*)d_in[12];
    const float* node_b2    = (const float*)d_in[13];
    const float* coord_W1   = (const float*)d_in[14];
    const float* coord_b1   = (const float*)d_in[15];
    const float* coord_W2   = (const float*)d_in[16];
    const float* lin_W      = (const float*)d_in[19];

    int n = in_sizes[0] / 3;
    int E = in_sizes[2] / 2;
    float* out = (float*)d_out;

    init_kernel<<<(n + 127) / 128, 128>>>(node_attrs, positions, proj_W,
                                          emb_in_W, emb_in_b, edge_W1, edge_b1, n);
    count_kernel<<<(E + 255) / 256, 256>>>(edge_index, E);
    nop_kernel<<<1, 32>>>();

    int eblocks = 444;
    int nblocks = (n + NTPB - 1) / NTPB;

    for (int l = 0; l < 2; l++) {
        edge_kernel<<<eblocks, EBLK>>>(
            edge_index, E,
            edge_W1 + l * H * 68,
            edge_W2 + l * H * H, edge_b2 + l * H,
            coord_W1 + l * H * H, coord_b1 + l * H,
            coord_W2 + l * H);
        node_kernel<<<nblocks, NTPB>>>(
            node_W1 + l * H * 2 * H, node_b1 + l * H,
            node_W2 + l * H * H,     node_b2 + l * H,
            (l == 0) ? edge_W1 + H * 68 : nullptr,
            (l == 0) ? edge_b1 + H      : nullptr,
            (l == 1) ? lin_W            : nullptr,
            out, n);
    }
}